// round 9
// baseline (speedup 1.0000x reference)
#include <cuda_runtime.h>
#include <cuda_bf16.h>
#include <cstdint>
#include <math.h>

#define BATCH 4
#define CCH   512
#define HW    4096
#define NGRP  32
#define CPG   16

// ---------------- scratch (device globals; no allocation) ----------------
__device__ float g_xn [(size_t)BATCH * CCH * HW];          // residual fp32 [b][c][i]
__device__ float g_xnt[(size_t)BATCH * HW * CCH];          // tf32, elem-perm [b][i][c']
__device__ __nv_bfloat16 g_xnb[(size_t)BATCH * HW * CCH];  // bf16, pair-perm [b][i][c'']
__device__ float g_q  [(size_t)BATCH * HW * CCH];          // tf32 [b][i][o']
__device__ float g_k  [(size_t)BATCH * HW * CCH];          // tf32 [b][i][o']
__device__ __nv_bfloat16 g_v [(size_t)BATCH * CCH * HW];   // bf16 [b][c][j'']
__device__ float g_sc [(size_t)BATCH * HW * HW];           // fp32 scores [b][i][j''] 256MB
__device__ __nv_bfloat16 g_p [(size_t)BATCH * HW * HW];    // bf16 probs  [b][i][j''] 128MB
__device__ __nv_bfloat16 g_ao[(size_t)BATCH * HW * CCH];   // bf16 [b][i][c'']
__device__ float g_wq [(size_t)2 * CCH * CCH];             // tf32 elem-perm [Wq;Wk]
__device__ __nv_bfloat16 g_wvb[(size_t)CCH * CCH];         // bf16 pair-perm Wv
__device__ __nv_bfloat16 g_wob[(size_t)CCH * CCH];         // bf16 pair-perm Wo

// ---------------- helpers ----------------
__device__ __forceinline__ uint32_t smem_u32(const void* p) {
    uint32_t a;
    asm("{ .reg .u64 t; cvta.to.shared.u64 t, %1; cvt.u32.u64 %0, t; }" : "=r"(a) : "l"(p));
    return a;
}
__device__ __forceinline__ void cp_async16(uint32_t s, const void* g) {
    asm volatile("cp.async.cg.shared.global [%0], [%1], 16;" :: "r"(s), "l"(g));
}
#define CP_COMMIT() asm volatile("cp.async.commit_group;" ::: "memory")
#define CP_WAIT(N)  asm volatile("cp.async.wait_group %0;" :: "n"(N) : "memory")

__device__ __forceinline__ float rtf(float f) {
    uint32_t r;
    asm("cvt.rna.tf32.f32 %0, %1;" : "=r"(r) : "f"(f));
    return __uint_as_float(r);
}
__device__ __forceinline__ int perm8(int j) { return ((j & 3) << 1) | ((j >> 2) & 1); }
__device__ __forceinline__ int permbf(int c) {
    return (c & ~15) | (perm8((c >> 1) & 7) << 1) | (c & 1);
}
__device__ __forceinline__ int permpair(int pi) {
    return (pi & ~7) | perm8(pi & 7);
}
__device__ __forceinline__ uint32_t pack_bf2(float lo, float hi) {
    __nv_bfloat162 h = __floats2bfloat162_rn(lo, hi);
    return *reinterpret_cast<uint32_t*>(&h);
}

__device__ __forceinline__ void mma_tf32(float* d, const uint32_t* a, const uint32_t* b) {
    asm volatile(
        "mma.sync.aligned.m16n8k8.row.col.f32.tf32.tf32.f32 "
        "{%0,%1,%2,%3}, {%4,%5,%6,%7}, {%8,%9}, {%0,%1,%2,%3};"
        : "+f"(d[0]), "+f"(d[1]), "+f"(d[2]), "+f"(d[3])
        : "r"(a[0]), "r"(a[1]), "r"(a[2]), "r"(a[3]), "r"(b[0]), "r"(b[1]));
}
__device__ __forceinline__ void mma_bf16(float* d, uint32_t a0, uint32_t a1, uint32_t a2,
                                         uint32_t a3, uint32_t b0, uint32_t b1) {
    asm volatile(
        "mma.sync.aligned.m16n8k16.row.col.f32.bf16.bf16.f32 "
        "{%0,%1,%2,%3}, {%4,%5,%6,%7}, {%8,%9}, {%0,%1,%2,%3};"
        : "+f"(d[0]), "+f"(d[1]), "+f"(d[2]), "+f"(d[3])
        : "r"(a0), "r"(a1), "r"(a2), "r"(a3), "r"(b0), "r"(b1));
}

// ---------------- weight prep ----------------
__global__ __launch_bounds__(256) void prep_w_kernel(const float* __restrict__ src,
                                                     float* __restrict__ dst, int n) {
    int i = blockIdx.x * 256 + threadIdx.x;
    if (i < n) {
        int col = i & 511, row = i >> 9;
        int c2 = (col & ~7) | perm8(col & 7);
        dst[(size_t)row * 512 + c2] = rtf(src[i]);
    }
}
__global__ __launch_bounds__(256) void prep_wb_kernel(const float* __restrict__ src,
                                                      __nv_bfloat16* __restrict__ dst, int n) {
    int i = blockIdx.x * 256 + threadIdx.x;
    if (i < n) {
        int col = i & 511, row = i >> 9;
        dst[(size_t)row * 512 + permbf(col)] = __float2bfloat16_rn(src[i]);
    }
}

// ---------------- GroupNorm ----------------
__global__ __launch_bounds__(256) void gn_kernel(const float* __restrict__ x,
                                                 const float* __restrict__ w,
                                                 const float* __restrict__ bias) {
    int bg = blockIdx.x;
    int b = bg / NGRP, g = bg % NGRP;
    const size_t base = ((size_t)(b * CCH + g * CPG)) * HW;
    const float4* x4 = (const float4*)(x + base);
    float4* o4 = (float4*)(g_xn + base);
    int t = threadIdx.x;
    const int N4 = (CPG * HW) / 4;

    float s = 0.f, ss = 0.f;
    for (int i = t; i < N4; i += 256) {
        float4 v = x4[i];
        s  += v.x + v.y + v.z + v.w;
        ss += v.x * v.x + v.y * v.y + v.z * v.z + v.w * v.w;
    }
    __shared__ float sh0[256], sh1[256];
    sh0[t] = s; sh1[t] = ss;
    __syncthreads();
    for (int off = 128; off; off >>= 1) {
        if (t < off) { sh0[t] += sh0[t + off]; sh1[t] += sh1[t + off]; }
        __syncthreads();
    }
    const float inv = 1.f / (float)(CPG * HW);
    float mean = sh0[0] * inv;
    float var  = sh1[0] * inv - mean * mean;
    float rstd = rsqrtf(var + 1e-5f);

    for (int i = t; i < N4; i += 256) {
        int c = g * CPG + ((i * 4) >> 12);
        float sw = w[c] * rstd;
        float sb = bias[c] - mean * sw;
        float4 v = x4[i];
        float4 o;
        o.x = v.x * sw + sb; o.y = v.y * sw + sb;
        o.z = v.z * sw + sb; o.w = v.w * sw + sb;
        o4[i] = o;
    }
}

// ---------------- transpose -> xnt (tf32 elem-perm) + xnb (bf16 pair-perm) ----------------
__global__ __launch_bounds__(256) void tr_kernel() {
    __shared__ float tile[32][33];
    int b = blockIdx.z;
    const float* in = g_xn + (size_t)b * CCH * HW;
    float* ot = g_xnt + (size_t)b * CCH * HW;
    __nv_bfloat16* ob = g_xnb + (size_t)b * CCH * HW;
    int i0 = blockIdx.x * 32;
    int c0 = blockIdx.y * 32;
    int tx = threadIdx.x & 31, ty = threadIdx.x >> 5;
#pragma unroll
    for (int j = 0; j < 32; j += 8)
        tile[ty + j][tx] = in[(size_t)(c0 + ty + j) * HW + i0 + tx];
    __syncthreads();
    const int c = c0 + tx;
    const int ct = c0 + ((tx & ~7) | perm8(tx & 7));
    const int cb = permbf(c);
#pragma unroll
    for (int j = 0; j < 32; j += 8) {
        float f = tile[tx][ty + j];
        ot[(size_t)(i0 + ty + j) * CCH + ct] = rtf(f);
        ob[(size_t)(i0 + ty + j) * CCH + cb] = __float2bfloat16_rn(f);
    }
}

// ---------------- big tf32 warp-MMA GEMM: 256x128 CTA tile, 64x64 warp tile ----------------
// D[m,n] = alpha * sum_k A[m,k]*B[n,k] (+epi). A/B tf32, K elem-permuted.
// QK=1: fused Q/K projection — bias[n], round+perm8 output cols, split writes to C (n<512) / C2.
// QK=0: scores — scale by alpha, output at bf16-pair-permuted columns (feeds bf16 GEMM k).
#define LDP 36
#define BIG_SMEM ((2 * 256 + 2 * 128) * LDP * 4)   // 110592

template<int QK>
__global__ __launch_bounds__(256, 1) void mm_big(
    const float* __restrict__ A, const float* __restrict__ B,
    float* __restrict__ C, float* __restrict__ C2,
    int Kd, int lda, int ldb, int ldc,
    size_t sA, size_t sB, size_t sC,
    float alpha, const float* __restrict__ bias)
{
    extern __shared__ float smf[];
    float* As[2] = { smf,             smf + 256 * LDP };
    float* Bs[2] = { smf + 512 * LDP, smf + 512 * LDP + 128 * LDP };
    const uint32_t sbase = smem_u32(smf);
    const uint32_t aoff[2] = { 0u, 256u * LDP * 4u };
    const uint32_t boff[2] = { 512u * LDP * 4u, (512u + 128u) * LDP * 4u };

    const int t = threadIdx.x;
    const int lane = t & 31, wid = t >> 5;
    const int gid = lane >> 2, qid = lane & 3;
    const int wm = (wid & 3) * 64, wn = (wid >> 2) * 64;

    const int bz = blockIdx.z;
    const float* Ab = A + (size_t)bz * sA;
    const float* Bb = B + (size_t)bz * sB;
    const int m0 = blockIdx.y * 256;
    const int n0 = blockIdx.x * 128;

    const int lrow = t >> 3;
    const int lk   = (t & 7) * 4;

    float acc[4][8][4];
#pragma unroll
    for (int mi = 0; mi < 4; mi++)
#pragma unroll
        for (int ni = 0; ni < 8; ni++)
#pragma unroll
            for (int j = 0; j < 4; j++) acc[mi][ni][j] = 0.f;

    const int nslab = Kd >> 5;

    {
        const float* ga = Ab + (size_t)(m0 + lrow) * lda + lk;
        const float* gb = Bb + (size_t)(n0 + lrow) * ldb + lk;
        uint32_t da = sbase + (uint32_t)((lrow * LDP + lk) * 4);
        uint32_t db = sbase + boff[0] + (uint32_t)((lrow * LDP + lk) * 4);
#pragma unroll
        for (int i = 0; i < 8; i++)
            cp_async16(da + i * 32u * LDP * 4u, ga + (size_t)(i * 32) * lda);
#pragma unroll
        for (int i = 0; i < 4; i++)
            cp_async16(db + i * 32u * LDP * 4u, gb + (size_t)(i * 32) * ldb);
        CP_COMMIT();
    }

    int buf = 0;
    for (int s = 0; s < nslab; s++) {
        if (s + 1 < nslab) {
            int k0 = (s + 1) << 5;
            int nb = buf ^ 1;
            const float* ga = Ab + (size_t)(m0 + lrow) * lda + k0 + lk;
            const float* gb = Bb + (size_t)(n0 + lrow) * ldb + k0 + lk;
            uint32_t da = sbase + aoff[nb] + (uint32_t)((lrow * LDP + lk) * 4);
            uint32_t db = sbase + boff[nb] + (uint32_t)((lrow * LDP + lk) * 4);
#pragma unroll
            for (int i = 0; i < 8; i++)
                cp_async16(da + i * 32u * LDP * 4u, ga + (size_t)(i * 32) * lda);
#pragma unroll
            for (int i = 0; i < 4; i++)
                cp_async16(db + i * 32u * LDP * 4u, gb + (size_t)(i * 32) * ldb);
            CP_COMMIT();
            CP_WAIT(1);
        } else {
            CP_WAIT(0);
        }
        __syncthreads();

        const float* as = As[buf];
        const float* bs = Bs[buf];
#pragma unroll
        for (int kk = 0; kk < 4; kk++) {
            const int kb = kk * 8;
            uint32_t afr[4][4];
#pragma unroll
            for (int mi = 0; mi < 4; mi++) {
                const float* ap = as + (wm + mi * 16 + gid) * LDP + kb + 2 * qid;
                float2 va = *(const float2*)ap;
                float2 vb = *(const float2*)(ap + 8 * LDP);
                afr[mi][0] = __float_as_uint(va.x);
                afr[mi][1] = __float_as_uint(vb.x);
                afr[mi][2] = __float_as_uint(va.y);
                afr[mi][3] = __float_as_uint(vb.y);
            }
            uint32_t bfr[8][2];
#pragma unroll
            for (int ni = 0; ni < 8; ni++) {
                float2 vb = *(const float2*)(bs + (wn + ni * 8 + gid) * LDP + kb + 2 * qid);
                bfr[ni][0] = __float_as_uint(vb.x);
                bfr[ni][1] = __float_as_uint(vb.y);
            }
#pragma unroll
            for (int mi = 0; mi < 4; mi++)
#pragma unroll
                for (int ni = 0; ni < 8; ni++)
                    mma_tf32(acc[mi][ni], afr[mi], bfr[ni]);
        }
        __syncthreads();
        buf ^= 1;
    }

    // epilogue
    const int j0 = qid * 2, j1 = qid * 2 + 1;
#pragma unroll
    for (int mi = 0; mi < 4; mi++) {
        const int r0 = m0 + wm + mi * 16 + gid;
        const int r1 = r0 + 8;
#pragma unroll
        for (int ni = 0; ni < 8; ni++) {
            const int colb = n0 + wn + ni * 8;
            float o00 = acc[mi][ni][0], o01 = acc[mi][ni][1];
            float o10 = acc[mi][ni][2], o11 = acc[mi][ni][3];
            if (QK) {
                float bn0 = bias[colb + j0], bn1 = bias[colb + j1];
                o00 = rtf(o00 + bn0); o01 = rtf(o01 + bn1);
                o10 = rtf(o10 + bn0); o11 = rtf(o11 + bn1);
                const int c0a = colb + perm8(j0);
                const int c1a = colb + perm8(j1);
                float* Cb;
                int cc0, cc1;
                if (colb < 512) { Cb = C  + (size_t)bz * sC; cc0 = c0a; cc1 = c1a; }
                else            { Cb = C2 + (size_t)bz * sC; cc0 = c0a - 512; cc1 = c1a - 512; }
                Cb[(size_t)r0 * ldc + cc0] = o00;
                Cb[(size_t)r0 * ldc + cc1] = o01;
                Cb[(size_t)r1 * ldc + cc0] = o10;
                Cb[(size_t)r1 * ldc + cc1] = o11;
            } else {
                o00 *= alpha; o01 *= alpha; o10 *= alpha; o11 *= alpha;
                float* Cb = C + (size_t)bz * sC;
                const int c0a = permbf(colb + j0);   // pair stays adjacent
                Cb[(size_t)r0 * ldc + c0a]     = o00;
                Cb[(size_t)r0 * ldc + c0a + 1] = o01;
                Cb[(size_t)r1 * ldc + c0a]     = o10;
                Cb[(size_t)r1 * ldc + c0a + 1] = o11;
            }
        }
    }
}

// ---------------- bf16 warp-MMA GEMM (V-proj, attn.V, out-proj) ----------------
#define LDPB 20
#define TILEB_BYTES (128 * LDPB * 4)
#define MMB_SMEM (4 * TILEB_BYTES)

template<int EPI, int OUTBF>
__global__ __launch_bounds__(256, 2) void mmb_kernel(
    const __nv_bfloat16* __restrict__ A, const __nv_bfloat16* __restrict__ B,
    void* __restrict__ Cv,
    int Kd, int lda, int ldb, int ldc,
    size_t sA, size_t sB, size_t sC,
    const float* __restrict__ bias,
    const float* __restrict__ resid, size_t sR)
{
    extern __shared__ uint32_t smu[];
    uint32_t* As[2] = { smu,                  smu + 128 * LDPB };
    uint32_t* Bs[2] = { smu + 2 * 128 * LDPB, smu + 3 * 128 * LDPB };
    const uint32_t sbase = smem_u32(smu);

    const int t = threadIdx.x;
    const int lane = t & 31, wid = t >> 5;
    const int gid = lane >> 2, qid = lane & 3;
    const int wm = (wid & 3) * 32, wn = (wid >> 2) * 64;

    const int bz = blockIdx.z;
    const __nv_bfloat16* Ab = A + (size_t)bz * sA;
    const __nv_bfloat16* Bb = B + (size_t)bz * sB;
    const int m0 = blockIdx.y * 128;
    const int n0 = blockIdx.x * 128;

    const int lrow = t >> 2;
    const int lch  = t & 3;

    float acc[2][8][4];
#pragma unroll
    for (int mi = 0; mi < 2; mi++)
#pragma unroll
        for (int ni = 0; ni < 8; ni++)
#pragma unroll
            for (int j = 0; j < 4; j++) acc[mi][ni][j] = 0.f;

    const int nslab = Kd >> 5;

    {
        const __nv_bfloat16* ga = Ab + (size_t)(m0 + lrow) * lda + lch * 8;
        const __nv_bfloat16* gb = Bb + (size_t)(n0 + lrow) * ldb + lch * 8;
        uint32_t da = sbase + (uint32_t)((lrow * LDPB + lch * 4) * 4);
        uint32_t db = da + 2u * TILEB_BYTES;
        cp_async16(da, ga);
        cp_async16(da + 64u * LDPB * 4u, ga + (size_t)64 * lda);
        cp_async16(db, gb);
        cp_async16(db + 64u * LDPB * 4u, gb + (size_t)64 * ldb);
        CP_COMMIT();
    }

    int buf = 0;
    for (int s = 0; s < nslab; s++) {
        if (s + 1 < nslab) {
            int k0 = (s + 1) << 5;
            int nb = buf ^ 1;
            const __nv_bfloat16* ga = Ab + (size_t)(m0 + lrow) * lda + k0 + lch * 8;
            const __nv_bfloat16* gb = Bb + (size_t)(n0 + lrow) * ldb + k0 + lch * 8;
            uint32_t da = sbase + (uint32_t)nb * TILEB_BYTES + (uint32_t)((lrow * LDPB + lch * 4) * 4);
            uint32_t db = da + 2u * TILEB_BYTES;
            cp_async16(da, ga);
            cp_async16(da + 64u * LDPB * 4u, ga + (size_t)64 * lda);
            cp_async16(db, gb);
            cp_async16(db + 64u * LDPB * 4u, gb + (size_t)64 * ldb);
            CP_COMMIT();
            CP_WAIT(1);
        } else {
            CP_WAIT(0);
        }
        __syncthreads();

        const uint32_t* as = As[buf];
        const uint32_t* bs = Bs[buf];
#pragma unroll
        for (int s2 = 0; s2 < 2; s2++) {
            const int kb = s2 * 8 + 2 * qid;
            uint32_t a0[2], a1[2], a2[2], a3[2];
#pragma unroll
            for (int mi = 0; mi < 2; mi++) {
                uint2 va = *(const uint2*)(as + (wm + mi * 16 + gid) * LDPB + kb);
                uint2 vb = *(const uint2*)(as + (wm + mi * 16 + gid + 8) * LDPB + kb);
                a0[mi] = va.x; a2[mi] = va.y;
                a1[mi] = vb.x; a3[mi] = vb.y;
            }
            uint2 bf[8];
#pragma unroll
            for (int ni = 0; ni < 8; ni++)
                bf[ni] = *(const uint2*)(bs + (wn + ni * 8 + gid) * LDPB + kb);
#pragma unroll
            for (int mi = 0; mi < 2; mi++)
#pragma unroll
                for (int ni = 0; ni < 8; ni++)
                    mma_bf16(acc[mi][ni], a0[mi], a1[mi], a2[mi], a3[mi], bf[ni].x, bf[ni].y);
        }
        __syncthreads();
        buf ^= 1;
    }

#pragma unroll
    for (int mi = 0; mi < 2; mi++) {
        const int r0 = m0 + wm + mi * 16 + gid;
        const int r1 = r0 + 8;
        float b0 = 0.f, b1 = 0.f;
        if (EPI == 1 || EPI == 3) { b0 = bias[r0]; b1 = bias[r1]; }
#pragma unroll
        for (int ni = 0; ni < 8; ni++) {
            const int colb = n0 + wn + ni * 8;
            const int col = colb + 2 * qid;
            float o00 = acc[mi][ni][0] + b0, o01 = acc[mi][ni][1] + b0;
            float o10 = acc[mi][ni][2] + b1, o11 = acc[mi][ni][3] + b1;
            if (OUTBF) {
                uint32_t* Cb = (uint32_t*)Cv + (size_t)bz * (sC >> 1);
                const int cp = permpair(col >> 1);
                Cb[(size_t)r0 * (ldc >> 1) + cp] = pack_bf2(o00, o01);
                Cb[(size_t)r1 * (ldc >> 1) + cp] = pack_bf2(o10, o11);
            } else {
                float* Cb = (float*)Cv + (size_t)bz * sC;
                if (EPI == 3) {
                    const float* rb = resid + (size_t)bz * sR;
                    float2 rv0 = *(const float2*)(rb + (size_t)r0 * ldc + col);
                    float2 rv1 = *(const float2*)(rb + (size_t)r1 * ldc + col);
                    o00 += rv0.x; o01 += rv0.y; o10 += rv1.x; o11 += rv1.y;
                }
                *(float2*)(Cb + (size_t)r0 * ldc + col) = make_float2(o00, o01);
                *(float2*)(Cb + (size_t)r1 * ldc + col) = make_float2(o10, o11);
            }
        }
    }
}

// ---------------- row softmax: fp32 g_sc -> bf16 g_p ----------------
__global__ __launch_bounds__(256) void softmax_kernel() {
    const float4* row = (const float4*)(g_sc + (size_t)blockIdx.x * HW);
    uint2* prow = (uint2*)(g_p + (size_t)blockIdx.x * HW);
    int t = threadIdx.x;
    float4 v[4];
    float mx = -1e30f;
#pragma unroll
    for (int i = 0; i < 4; i++) {
        v[i] = row[t + i * 256];
        mx = fmaxf(mx, fmaxf(fmaxf(v[i].x, v[i].y), fmaxf(v[i].z, v[i].w)));
    }
    __shared__ float sh[8];
#pragma unroll
    for (int o = 16; o; o >>= 1) mx = fmaxf(mx, __shfl_xor_sync(0xffffffffu, mx, o));
    if ((t & 31) == 0) sh[t >> 5] = mx;
    __syncthreads();
    mx = sh[0];
#pragma unroll
    for (int i = 1; i < 8; i++) mx = fmaxf(mx, sh[i]);

    float s = 0.f;
#pragma unroll
    for (int i = 0; i < 4; i++) {
        v[i].x = __expf(v[i].x - mx); v[i].y = __expf(v[i].y - mx);
        v[i].z = __expf(v[i].z - mx); v[i].w = __expf(v[i].w - mx);
        s += v[i].x + v[i].y + v[i].z + v[i].w;
    }
#pragma unroll
    for (int o = 16; o; o >>= 1) s += __shfl_xor_sync(0xffffffffu, s, o);
    __syncthreads();
    if ((t & 31) == 0) sh[t >> 5] = s;
    __syncthreads();
    s = 0.f;
#pragma unroll
    for (int i = 0; i < 8; i++) s += sh[i];
    float inv = 1.f / s;
#pragma unroll
    for (int i = 0; i < 4; i++) {
        uint2 o;
        o.x = pack_bf2(v[i].x * inv, v[i].y * inv);
        o.y = pack_bf2(v[i].z * inv, v[i].w * inv);
        prow[t + i * 256] = o;
    }
}

// ---------------- launch ----------------
extern "C" void kernel_launch(void* const* d_in, const int* in_sizes, int n_in,
                              void* d_out, int out_size) {
    const float* x     = (const float*)d_in[0];
    const float* gn_w  = (const float*)d_in[1];
    const float* gn_b  = (const float*)d_in[2];
    const float* qkv_w = (const float*)d_in[3];
    const float* qkv_b = (const float*)d_in[4];
    const float* out_w = (const float*)d_in[5];
    const float* out_b = (const float*)d_in[6];
    float* out = (float*)d_out;

    float *xn, *xnt, *q, *k, *sc, *wq;
    __nv_bfloat16 *xnb, *v, *p, *ao, *wvb, *wob;
    cudaGetSymbolAddress((void**)&xn,  g_xn);
    cudaGetSymbolAddress((void**)&xnt, g_xnt);
    cudaGetSymbolAddress((void**)&xnb, g_xnb);
    cudaGetSymbolAddress((void**)&q,   g_q);
    cudaGetSymbolAddress((void**)&k,   g_k);
    cudaGetSymbolAddress((void**)&v,   g_v);
    cudaGetSymbolAddress((void**)&sc,  g_sc);
    cudaGetSymbolAddress((void**)&p,   g_p);
    cudaGetSymbolAddress((void**)&ao,  g_ao);
    cudaGetSymbolAddress((void**)&wq,  g_wq);
    cudaGetSymbolAddress((void**)&wvb, g_wvb);
    cudaGetSymbolAddress((void**)&wob, g_wob);

    cudaFuncSetAttribute(mm_big<1>, cudaFuncAttributeMaxDynamicSharedMemorySize, BIG_SMEM);
    cudaFuncSetAttribute(mm_big<0>, cudaFuncAttributeMaxDynamicSharedMemorySize, BIG_SMEM);
    cudaFuncSetAttribute(mmb_kernel<1,1>, cudaFuncAttributeMaxDynamicSharedMemorySize, MMB_SMEM);
    cudaFuncSetAttribute(mmb_kernel<0,1>, cudaFuncAttributeMaxDynamicSharedMemorySize, MMB_SMEM);
    cudaFuncSetAttribute(mmb_kernel<3,0>, cudaFuncAttributeMaxDynamicSharedMemorySize, MMB_SMEM);

    const size_t sXN = (size_t)CCH * HW;
    const size_t sSC = (size_t)HW * HW;

    // 0) weight prep
    prep_w_kernel<<<(2 * CCH * CCH + 255) / 256, 256>>>(qkv_w, wq, 2 * CCH * CCH);
    prep_wb_kernel<<<(CCH * CCH + 255) / 256, 256>>>(qkv_w + (size_t)2 * CCH * CCH, wvb, CCH * CCH);
    prep_wb_kernel<<<(CCH * CCH + 255) / 256, 256>>>(out_w, wob, CCH * CCH);

    // 1) GroupNorm
    gn_kernel<<<BATCH * NGRP, 256>>>(x, gn_w, gn_b);
    // 2) transpose -> xnt (tf32) + xnb (bf16)
    tr_kernel<<<dim3(HW / 32, CCH / 32, BATCH), 256>>>();

    // 3+4) fused Q,K projection: N=1024 over [Wq;Wk], bias qkv_b[0..1023]
    mm_big<1><<<dim3(1024 / 128, HW / 256, BATCH), 256, BIG_SMEM>>>(
        xnt, wq, q, k, CCH, CCH, CCH, CCH, sXN, 0, sXN, 1.f, qkv_b);

    // 5) V[c,j''] = Wv[c,:] . xn[:,j] + bv   (bf16)
    mmb_kernel<1,1><<<dim3(HW / 128, CCH / 128, BATCH), 256, MMB_SMEM>>>(
        wvb, xnb, v, CCH, CCH, CCH, HW, 0, sXN, sXN, qkv_b + 2 * CCH, nullptr, 0);

    // 6) scores[i,j''] = scale * Q[i,:].K[j,:]  (tf32 256x128, out at bf16-pair positions)
    mm_big<0><<<dim3(HW / 128, HW / 256, BATCH), 256, BIG_SMEM>>>(
        q, k, sc, nullptr, CCH, CCH, CCH, HW, sXN, sXN, sSC,
        0.044194173824159216f, nullptr);

    // 7) softmax -> bf16 P
    softmax_kernel<<<BATCH * HW, 256>>>();

    // 8) ao[i,c''] = P[i,:] . V[c,:]   (bf16)
    mmb_kernel<0,1><<<dim3(CCH / 128, HW / 128, BATCH), 256, MMB_SMEM>>>(
        p, v, ao, HW, HW, HW, CCH, sSC, sXN, sXN, nullptr, nullptr, 0);

    // 9) out[o,i] = Wo[o,:] . ao[i,:] + bo + xn[o,i]   (bf16 MMA, fp32 out)
    mmb_kernel<3,0><<<dim3(HW / 128, CCH / 128, BATCH), 256, MMB_SMEM>>>(
        wob, ao, out, CCH, CCH, CCH, HW, 0, sXN, sXN, out_b, xn, sXN);
}

// round 12
// speedup vs baseline: 1.5280x; 1.5280x over previous
#include <cuda_runtime.h>
#include <cuda_bf16.h>
#include <cstdint>
#include <math.h>

#define BATCH 4
#define CCH   512
#define HW    4096
#define NGRP  32
#define CPG   16

// ---------------- scratch (device globals; no allocation) ----------------
__device__ float g_xn [(size_t)BATCH * CCH * HW];          // residual fp32 [b][c][i]
__device__ float g_xnt[(size_t)BATCH * HW * CCH];          // tf32 [b][i][c]
__device__ __nv_bfloat16 g_xnb[(size_t)BATCH * HW * CCH];  // bf16 [b][i][c]
__device__ float g_q  [(size_t)BATCH * HW * CCH];          // tf32 [b][i][o]
__device__ float g_k  [(size_t)BATCH * HW * CCH];          // tf32 [b][i][o]
__device__ __nv_bfloat16 g_v [(size_t)BATCH * CCH * HW];   // bf16 [b][c][j]
__device__ float g_sc [(size_t)BATCH * HW * HW];           // fp32 scores 256MB
__device__ __nv_bfloat16 g_p [(size_t)BATCH * HW * HW];    // bf16 probs 128MB
__device__ __nv_bfloat16 g_ao[(size_t)BATCH * HW * CCH];   // bf16 [b][i][c]
__device__ float g_wq [(size_t)2 * CCH * CCH];             // tf32 [Wq;Wk]
__device__ __nv_bfloat16 g_wvb[(size_t)CCH * CCH];         // bf16 Wv
__device__ __nv_bfloat16 g_wob[(size_t)CCH * CCH];         // bf16 Wo

// ---------------- helpers ----------------
__device__ __forceinline__ uint32_t smem_u32(const void* p) {
    uint32_t a;
    asm("{ .reg .u64 t; cvta.to.shared.u64 t, %1; cvt.u32.u64 %0, t; }" : "=r"(a) : "l"(p));
    return a;
}
__device__ __forceinline__ void cp_async16(uint32_t s, const void* g) {
    asm volatile("cp.async.cg.shared.global [%0], [%1], 16;" :: "r"(s), "l"(g));
}
#define CP_COMMIT() asm volatile("cp.async.commit_group;" ::: "memory")
#define CP_WAIT(N)  asm volatile("cp.async.wait_group %0;" :: "n"(N) : "memory")

__device__ __forceinline__ float rtf(float f) {
    uint32_t r;
    asm("cvt.rna.tf32.f32 %0, %1;" : "=r"(r) : "f"(f));
    return __uint_as_float(r);
}
__device__ __forceinline__ uint32_t pack_bf2(float lo, float hi) {
    __nv_bfloat162 h = __floats2bfloat162_rn(lo, hi);
    return *reinterpret_cast<uint32_t*>(&h);
}
__device__ __forceinline__ void ldmx4(uint32_t* r, uint32_t addr) {
    asm volatile("ldmatrix.sync.aligned.m8n8.x4.shared.b16 {%0,%1,%2,%3}, [%4];"
                 : "=r"(r[0]), "=r"(r[1]), "=r"(r[2]), "=r"(r[3]) : "r"(addr));
}

__device__ __forceinline__ void mma_tf32(float* d, const uint32_t* a, const uint32_t* b) {
    asm volatile(
        "mma.sync.aligned.m16n8k8.row.col.f32.tf32.tf32.f32 "
        "{%0,%1,%2,%3}, {%4,%5,%6,%7}, {%8,%9}, {%0,%1,%2,%3};"
        : "+f"(d[0]), "+f"(d[1]), "+f"(d[2]), "+f"(d[3])
        : "r"(a[0]), "r"(a[1]), "r"(a[2]), "r"(a[3]), "r"(b[0]), "r"(b[1]));
}
__device__ __forceinline__ void mma_bf16(float* d, const uint32_t* a, const uint32_t* b) {
    asm volatile(
        "mma.sync.aligned.m16n8k16.row.col.f32.bf16.bf16.f32 "
        "{%0,%1,%2,%3}, {%4,%5,%6,%7}, {%8,%9}, {%0,%1,%2,%3};"
        : "+f"(d[0]), "+f"(d[1]), "+f"(d[2]), "+f"(d[3])
        : "r"(a[0]), "r"(a[1]), "r"(a[2]), "r"(a[3]), "r"(b[0]), "r"(b[1]));
}

// ---------------- weight prep (round/convert, identity layout) ----------------
__global__ __launch_bounds__(256) void prep_w_kernel(const float* __restrict__ src,
                                                     float* __restrict__ dst, int n) {
    int i = blockIdx.x * 256 + threadIdx.x;
    if (i < n) dst[i] = rtf(src[i]);
}
__global__ __launch_bounds__(256) void prep_wb_kernel(const float* __restrict__ src,
                                                      __nv_bfloat16* __restrict__ dst, int n) {
    int i = blockIdx.x * 256 + threadIdx.x;
    if (i < n) dst[i] = __float2bfloat16_rn(src[i]);
}

// ---------------- GroupNorm ----------------
__global__ __launch_bounds__(256) void gn_kernel(const float* __restrict__ x,
                                                 const float* __restrict__ w,
                                                 const float* __restrict__ bias) {
    int bg = blockIdx.x;
    int b = bg / NGRP, g = bg % NGRP;
    const size_t base = ((size_t)(b * CCH + g * CPG)) * HW;
    const float4* x4 = (const float4*)(x + base);
    float4* o4 = (float4*)(g_xn + base);
    int t = threadIdx.x;
    const int N4 = (CPG * HW) / 4;

    float s = 0.f, ss = 0.f;
    for (int i = t; i < N4; i += 256) {
        float4 v = x4[i];
        s  += v.x + v.y + v.z + v.w;
        ss += v.x * v.x + v.y * v.y + v.z * v.z + v.w * v.w;
    }
    __shared__ float sh0[256], sh1[256];
    sh0[t] = s; sh1[t] = ss;
    __syncthreads();
    for (int off = 128; off; off >>= 1) {
        if (t < off) { sh0[t] += sh0[t + off]; sh1[t] += sh1[t + off]; }
        __syncthreads();
    }
    const float inv = 1.f / (float)(CPG * HW);
    float mean = sh0[0] * inv;
    float var  = sh1[0] * inv - mean * mean;
    float rstd = rsqrtf(var + 1e-5f);

    for (int i = t; i < N4; i += 256) {
        int c = g * CPG + ((i * 4) >> 12);
        float sw = w[c] * rstd;
        float sb = bias[c] - mean * sw;
        float4 v = x4[i];
        float4 o;
        o.x = v.x * sw + sb; o.y = v.y * sw + sb;
        o.z = v.z * sw + sb; o.w = v.w * sw + sb;
        o4[i] = o;
    }
}

// ---------------- transpose -> xnt (tf32) + xnb (bf16), identity cols ----------------
__global__ __launch_bounds__(256) void tr_kernel() {
    __shared__ float tile[32][33];
    int b = blockIdx.z;
    const float* in = g_xn + (size_t)b * CCH * HW;
    float* ot = g_xnt + (size_t)b * CCH * HW;
    __nv_bfloat16* ob = g_xnb + (size_t)b * CCH * HW;
    int i0 = blockIdx.x * 32;
    int c0 = blockIdx.y * 32;
    int tx = threadIdx.x & 31, ty = threadIdx.x >> 5;
#pragma unroll
    for (int j = 0; j < 32; j += 8)
        tile[ty + j][tx] = in[(size_t)(c0 + ty + j) * HW + i0 + tx];
    __syncthreads();
    const int c = c0 + tx;
#pragma unroll
    for (int j = 0; j < 32; j += 8) {
        float f = tile[tx][ty + j];
        ot[(size_t)(i0 + ty + j) * CCH + c] = rtf(f);
        ob[(size_t)(i0 + ty + j) * CCH + c] = __float2bfloat16_rn(f);
    }
}

// ---------------- tf32 warp-MMA GEMM via ldmatrix (fused QK / scores) ----------------
// D[m,n] = alpha * sum_k A[m,k]*B[n,k]. Tile 128x128, K-slab 32, 8 warps (4m x 2n), warp 32x64.
// MODE 1: fused QK — +bias[n], rtf, split writes C (n<512) / C2 (n>=512).
// MODE 0: scores — alpha scale, fp32 out.
#define LDP 36
#define TILE_BYTES (128 * LDP * 4)
#define MM_SMEM (4 * TILE_BYTES)

template<int MODE>
__global__ __launch_bounds__(256, 2) void mmt_kernel(
    const float* __restrict__ A, const float* __restrict__ B,
    float* __restrict__ C, float* __restrict__ C2,
    int Kd, int lda, int ldb, int ldc,
    size_t sA, size_t sB, size_t sC,
    float alpha, const float* __restrict__ bias)
{
    extern __shared__ float smf[];
    const uint32_t sbase = smem_u32(smf);

    const int t = threadIdx.x;
    const int lane = t & 31, wid = t >> 5;
    const int gid = lane >> 2, qid = lane & 3;
    const int wm = (wid & 3) * 32, wn = (wid >> 2) * 64;

    const int bz = blockIdx.z;
    const float* Ab = A + (size_t)bz * sA;
    const float* Bb = B + (size_t)bz * sB;
    const int m0 = blockIdx.y * 128;
    const int n0 = blockIdx.x * 128;

    const int lrow = t >> 3;
    const int lk   = (t & 7) * 4;

    // ldmatrix per-lane offsets (in floats, within a tile)
    const int a_row  = wm + (lane & 15);
    const int a_fadd = (lane >> 4) << 2;
    const int b_row  = wn + ((lane & 16) >> 1) + (lane & 7);
    const int b_fadd = (lane & 8) ? 4 : 0;

    float acc[2][8][4];
#pragma unroll
    for (int mi = 0; mi < 2; mi++)
#pragma unroll
        for (int ni = 0; ni < 8; ni++)
#pragma unroll
            for (int j = 0; j < 4; j++) acc[mi][ni][j] = 0.f;

    const int nslab = Kd >> 5;

    {
        const float* ga = Ab + (size_t)(m0 + lrow) * lda + lk;
        const float* gb = Bb + (size_t)(n0 + lrow) * ldb + lk;
        uint32_t da = sbase + (uint32_t)((lrow * LDP + lk) * 4);
        uint32_t db = da + 2u * TILE_BYTES;
#pragma unroll
        for (int i = 0; i < 4; i++) {
            cp_async16(da + i * 32u * LDP * 4u, ga + (size_t)(i * 32) * lda);
            cp_async16(db + i * 32u * LDP * 4u, gb + (size_t)(i * 32) * ldb);
        }
        CP_COMMIT();
    }

    int buf = 0;
    for (int s = 0; s < nslab; s++) {
        if (s + 1 < nslab) {
            int k0 = (s + 1) << 5;
            int nb = buf ^ 1;
            const float* ga = Ab + (size_t)(m0 + lrow) * lda + k0 + lk;
            const float* gb = Bb + (size_t)(n0 + lrow) * ldb + k0 + lk;
            uint32_t da = sbase + (uint32_t)nb * TILE_BYTES + (uint32_t)((lrow * LDP + lk) * 4);
            uint32_t db = da + 2u * TILE_BYTES;
#pragma unroll
            for (int i = 0; i < 4; i++) {
                cp_async16(da + i * 32u * LDP * 4u, ga + (size_t)(i * 32) * lda);
                cp_async16(db + i * 32u * LDP * 4u, gb + (size_t)(i * 32) * ldb);
            }
            CP_COMMIT();
            CP_WAIT(1);
        } else {
            CP_WAIT(0);
        }
        __syncthreads();

        const uint32_t abase = sbase + (uint32_t)buf * TILE_BYTES;
        const uint32_t bbase = abase + 2u * TILE_BYTES;
#pragma unroll
        for (int kk = 0; kk < 4; kk++) {
            const int kb = kk * 8;
            uint32_t afr[2][4];
#pragma unroll
            for (int mi = 0; mi < 2; mi++)
                ldmx4(afr[mi], abase + (uint32_t)(((a_row + mi * 16) * LDP + kb + a_fadd) * 4));
            uint32_t bfr[8][2];
#pragma unroll
            for (int nj = 0; nj < 4; nj++) {
                uint32_t r[4];
                ldmx4(r, bbase + (uint32_t)(((b_row + nj * 16) * LDP + kb + b_fadd) * 4));
                bfr[2 * nj][0] = r[0]; bfr[2 * nj][1] = r[1];
                bfr[2 * nj + 1][0] = r[2]; bfr[2 * nj + 1][1] = r[3];
            }
#pragma unroll
            for (int mi = 0; mi < 2; mi++)
#pragma unroll
                for (int ni = 0; ni < 8; ni++)
                    mma_tf32(acc[mi][ni], afr[mi], bfr[ni]);
        }
        __syncthreads();
        buf ^= 1;
    }

    // epilogue (identity columns)
    const int j0 = qid * 2, j1 = qid * 2 + 1;
#pragma unroll
    for (int mi = 0; mi < 2; mi++) {
        const int r0 = m0 + wm + mi * 16 + gid;
        const int r1 = r0 + 8;
#pragma unroll
        for (int ni = 0; ni < 8; ni++) {
            const int colb = n0 + wn + ni * 8;
            float o00 = acc[mi][ni][0], o01 = acc[mi][ni][1];
            float o10 = acc[mi][ni][2], o11 = acc[mi][ni][3];
            if (MODE == 1) {
                float bn0 = bias[colb + j0], bn1 = bias[colb + j1];
                o00 = rtf(o00 + bn0); o01 = rtf(o01 + bn1);
                o10 = rtf(o10 + bn0); o11 = rtf(o11 + bn1);
                float* Cb;
                int cc;
                if (colb < 512) { Cb = C  + (size_t)bz * sC; cc = colb + j0; }
                else            { Cb = C2 + (size_t)bz * sC; cc = colb + j0 - 512; }
                *(float2*)(Cb + (size_t)r0 * ldc + cc) = make_float2(o00, o01);
                *(float2*)(Cb + (size_t)r1 * ldc + cc) = make_float2(o10, o11);
            } else {
                o00 *= alpha; o01 *= alpha; o10 *= alpha; o11 *= alpha;
                float* Cb = C + (size_t)bz * sC;
                *(float2*)(Cb + (size_t)r0 * ldc + colb + j0) = make_float2(o00, o01);
                *(float2*)(Cb + (size_t)r1 * ldc + colb + j0) = make_float2(o10, o11);
            }
        }
    }
}

// ---------------- bf16 warp-MMA GEMM via ldmatrix ----------------
// EPI: 0=none, 1=+bias[m], 3=+bias[m]+resid (fp32 out). OUTBF: 1=bf16 out, 0=fp32 out.
#define LDPB 20
#define TILEB_BYTES (128 * LDPB * 4)
#define MMB_SMEM (4 * TILEB_BYTES)

template<int EPI, int OUTBF>
__global__ __launch_bounds__(256, 2) void mmb_kernel(
    const __nv_bfloat16* __restrict__ A, const __nv_bfloat16* __restrict__ B,
    void* __restrict__ Cv,
    int Kd, int lda, int ldb, int ldc,
    size_t sA, size_t sB, size_t sC,
    const float* __restrict__ bias,
    const float* __restrict__ resid, size_t sR)
{
    extern __shared__ uint32_t smu[];
    const uint32_t sbase = smem_u32(smu);

    const int t = threadIdx.x;
    const int lane = t & 31, wid = t >> 5;
    const int gid = lane >> 2, qid = lane & 3;
    const int wm = (wid & 3) * 32, wn = (wid >> 2) * 64;

    const int bz = blockIdx.z;
    const __nv_bfloat16* Ab = A + (size_t)bz * sA;
    const __nv_bfloat16* Bb = B + (size_t)bz * sB;
    const int m0 = blockIdx.y * 128;
    const int n0 = blockIdx.x * 128;

    const int lrow = t >> 2;
    const int lch  = t & 3;

    const int a_row  = wm + (lane & 15);
    const int a_uadd = (lane >> 4) << 2;            // u32 offset
    const int b_row  = wn + ((lane & 16) >> 1) + (lane & 7);
    const int b_uadd = (lane & 8) ? 4 : 0;

    float acc[2][8][4];
#pragma unroll
    for (int mi = 0; mi < 2; mi++)
#pragma unroll
        for (int ni = 0; ni < 8; ni++)
#pragma unroll
            for (int j = 0; j < 4; j++) acc[mi][ni][j] = 0.f;

    const int nslab = Kd >> 5;

    {
        const __nv_bfloat16* ga = Ab + (size_t)(m0 + lrow) * lda + lch * 8;
        const __nv_bfloat16* gb = Bb + (size_t)(n0 + lrow) * ldb + lch * 8;
        uint32_t da = sbase + (uint32_t)((lrow * LDPB + lch * 4) * 4);
        uint32_t db = da + 2u * TILEB_BYTES;
        cp_async16(da, ga);
        cp_async16(da + 64u * LDPB * 4u, ga + (size_t)64 * lda);
        cp_async16(db, gb);
        cp_async16(db + 64u * LDPB * 4u, gb + (size_t)64 * ldb);
        CP_COMMIT();
    }

    int buf = 0;
    for (int s = 0; s < nslab; s++) {
        if (s + 1 < nslab) {
            int k0 = (s + 1) << 5;
            int nb = buf ^ 1;
            const __nv_bfloat16* ga = Ab + (size_t)(m0 + lrow) * lda + k0 + lch * 8;
            const __nv_bfloat16* gb = Bb + (size_t)(n0 + lrow) * ldb + k0 + lch * 8;
            uint32_t da = sbase + (uint32_t)nb * TILEB_BYTES + (uint32_t)((lrow * LDPB + lch * 4) * 4);
            uint32_t db = da + 2u * TILEB_BYTES;
            cp_async16(da, ga);
            cp_async16(da + 64u * LDPB * 4u, ga + (size_t)64 * lda);
            cp_async16(db, gb);
            cp_async16(db + 64u * LDPB * 4u, gb + (size_t)64 * ldb);
            CP_COMMIT();
            CP_WAIT(1);
        } else {
            CP_WAIT(0);
        }
        __syncthreads();

        const uint32_t abase = sbase + (uint32_t)buf * TILEB_BYTES;
        const uint32_t bbase = abase + 2u * TILEB_BYTES;
#pragma unroll
        for (int s2 = 0; s2 < 2; s2++) {
            const int kb = s2 * 8;
            uint32_t afr[2][4];
#pragma unroll
            for (int mi = 0; mi < 2; mi++)
                ldmx4(afr[mi], abase + (uint32_t)(((a_row + mi * 16) * LDPB + kb + a_uadd) * 4));
            uint32_t bfr[8][2];
#pragma unroll
            for (int nj = 0; nj < 4; nj++) {
                uint32_t r[4];
                ldmx4(r, bbase + (uint32_t)(((b_row + nj * 16) * LDPB + kb + b_uadd) * 4));
                bfr[2 * nj][0] = r[0]; bfr[2 * nj][1] = r[1];
                bfr[2 * nj + 1][0] = r[2]; bfr[2 * nj + 1][1] = r[3];
            }
#pragma unroll
            for (int mi = 0; mi < 2; mi++)
#pragma unroll
                for (int ni = 0; ni < 8; ni++)
                    mma_bf16(acc[mi][ni], afr[mi], bfr[ni]);
        }
        __syncthreads();
        buf ^= 1;
    }

#pragma unroll
    for (int mi = 0; mi < 2; mi++) {
        const int r0 = m0 + wm + mi * 16 + gid;
        const int r1 = r0 + 8;
        float b0 = 0.f, b1 = 0.f;
        if (EPI == 1 || EPI == 3) { b0 = bias[r0]; b1 = bias[r1]; }
#pragma unroll
        for (int ni = 0; ni < 8; ni++) {
            const int col = n0 + wn + ni * 8 + 2 * qid;
            float o00 = acc[mi][ni][0] + b0, o01 = acc[mi][ni][1] + b0;
            float o10 = acc[mi][ni][2] + b1, o11 = acc[mi][ni][3] + b1;
            if (OUTBF) {
                uint32_t* Cb = (uint32_t*)Cv + (size_t)bz * (sC >> 1);
                const int cp = col >> 1;
                Cb[(size_t)r0 * (ldc >> 1) + cp] = pack_bf2(o00, o01);
                Cb[(size_t)r1 * (ldc >> 1) + cp] = pack_bf2(o10, o11);
            } else {
                float* Cb = (float*)Cv + (size_t)bz * sC;
                if (EPI == 3) {
                    const float* rb = resid + (size_t)bz * sR;
                    float2 rv0 = *(const float2*)(rb + (size_t)r0 * ldc + col);
                    float2 rv1 = *(const float2*)(rb + (size_t)r1 * ldc + col);
                    o00 += rv0.x; o01 += rv0.y; o10 += rv1.x; o11 += rv1.y;
                }
                *(float2*)(Cb + (size_t)r0 * ldc + col) = make_float2(o00, o01);
                *(float2*)(Cb + (size_t)r1 * ldc + col) = make_float2(o10, o11);
            }
        }
    }
}

// ---------------- row softmax: fp32 g_sc -> bf16 g_p ----------------
__global__ __launch_bounds__(256) void softmax_kernel() {
    const float4* row = (const float4*)(g_sc + (size_t)blockIdx.x * HW);
    uint2* prow = (uint2*)(g_p + (size_t)blockIdx.x * HW);
    int t = threadIdx.x;
    float4 v[4];
    float mx = -1e30f;
#pragma unroll
    for (int i = 0; i < 4; i++) {
        v[i] = row[t + i * 256];
        mx = fmaxf(mx, fmaxf(fmaxf(v[i].x, v[i].y), fmaxf(v[i].z, v[i].w)));
    }
    __shared__ float sh[8];
#pragma unroll
    for (int o = 16; o; o >>= 1) mx = fmaxf(mx, __shfl_xor_sync(0xffffffffu, mx, o));
    if ((t & 31) == 0) sh[t >> 5] = mx;
    __syncthreads();
    mx = sh[0];
#pragma unroll
    for (int i = 1; i < 8; i++) mx = fmaxf(mx, sh[i]);

    float s = 0.f;
#pragma unroll
    for (int i = 0; i < 4; i++) {
        v[i].x = __expf(v[i].x - mx); v[i].y = __expf(v[i].y - mx);
        v[i].z = __expf(v[i].z - mx); v[i].w = __expf(v[i].w - mx);
        s += v[i].x + v[i].y + v[i].z + v[i].w;
    }
#pragma unroll
    for (int o = 16; o; o >>= 1) s += __shfl_xor_sync(0xffffffffu, s, o);
    __syncthreads();
    if ((t & 31) == 0) sh[t >> 5] = s;
    __syncthreads();
    s = 0.f;
#pragma unroll
    for (int i = 0; i < 8; i++) s += sh[i];
    float inv = 1.f / s;
#pragma unroll
    for (int i = 0; i < 4; i++) {
        uint2 o;
        o.x = pack_bf2(v[i].x * inv, v[i].y * inv);
        o.y = pack_bf2(v[i].z * inv, v[i].w * inv);
        prow[t + i * 256] = o;
    }
}

// ---------------- launch ----------------
extern "C" void kernel_launch(void* const* d_in, const int* in_sizes, int n_in,
                              void* d_out, int out_size) {
    const float* x     = (const float*)d_in[0];
    const float* gn_w  = (const float*)d_in[1];
    const float* gn_b  = (const float*)d_in[2];
    const float* qkv_w = (const float*)d_in[3];
    const float* qkv_b = (const float*)d_in[4];
    const float* out_w = (const float*)d_in[5];
    const float* out_b = (const float*)d_in[6];
    float* out = (float*)d_out;

    float *xn, *xnt, *q, *k, *sc, *wq;
    __nv_bfloat16 *xnb, *v, *p, *ao, *wvb, *wob;
    cudaGetSymbolAddress((void**)&xn,  g_xn);
    cudaGetSymbolAddress((void**)&xnt, g_xnt);
    cudaGetSymbolAddress((void**)&xnb, g_xnb);
    cudaGetSymbolAddress((void**)&q,   g_q);
    cudaGetSymbolAddress((void**)&k,   g_k);
    cudaGetSymbolAddress((void**)&v,   g_v);
    cudaGetSymbolAddress((void**)&sc,  g_sc);
    cudaGetSymbolAddress((void**)&p,   g_p);
    cudaGetSymbolAddress((void**)&ao,  g_ao);
    cudaGetSymbolAddress((void**)&wq,  g_wq);
    cudaGetSymbolAddress((void**)&wvb, g_wvb);
    cudaGetSymbolAddress((void**)&wob, g_wob);

    cudaFuncSetAttribute(mmt_kernel<1>, cudaFuncAttributeMaxDynamicSharedMemorySize, MM_SMEM);
    cudaFuncSetAttribute(mmt_kernel<0>, cudaFuncAttributeMaxDynamicSharedMemorySize, MM_SMEM);
    cudaFuncSetAttribute(mmb_kernel<1,1>, cudaFuncAttributeMaxDynamicSharedMemorySize, MMB_SMEM);
    cudaFuncSetAttribute(mmb_kernel<0,1>, cudaFuncAttributeMaxDynamicSharedMemorySize, MMB_SMEM);
    cudaFuncSetAttribute(mmb_kernel<3,0>, cudaFuncAttributeMaxDynamicSharedMemorySize, MMB_SMEM);

    const size_t sXN = (size_t)CCH * HW;
    const size_t sSC = (size_t)HW * HW;

    // 0) weight prep
    prep_w_kernel<<<(2 * CCH * CCH + 255) / 256, 256>>>(qkv_w, wq, 2 * CCH * CCH);
    prep_wb_kernel<<<(CCH * CCH + 255) / 256, 256>>>(qkv_w + (size_t)2 * CCH * CCH, wvb, CCH * CCH);
    prep_wb_kernel<<<(CCH * CCH + 255) / 256, 256>>>(out_w, wob, CCH * CCH);

    // 1) GroupNorm
    gn_kernel<<<BATCH * NGRP, 256>>>(x, gn_w, gn_b);
    // 2) transpose -> xnt (tf32) + xnb (bf16)
    tr_kernel<<<dim3(HW / 32, CCH / 32, BATCH), 256>>>();

    // 3+4) fused Q,K projection: N=1024 over [Wq;Wk]
    mmt_kernel<1><<<dim3(1024 / 128, HW / 128, BATCH), 256, MM_SMEM>>>(
        xnt, wq, q, k, CCH, CCH, CCH, CCH, sXN, 0, sXN, 1.f, qkv_b);

    // 5) V[c,j] = Wv[c,:] . xn[:,j] + bv   (bf16)
    mmb_kernel<1,1><<<dim3(HW / 128, CCH / 128, BATCH), 256, MMB_SMEM>>>(
        wvb, xnb, v, CCH, CCH, CCH, HW, 0, sXN, sXN, qkv_b + 2 * CCH, nullptr, 0);

    // 6) scores[i,j] = scale * Q[i,:].K[j,:]  (tf32)
    mmt_kernel<0><<<dim3(HW / 128, HW / 128, BATCH), 256, MM_SMEM>>>(
        q, k, sc, nullptr, CCH, CCH, CCH, HW, sXN, sXN, sSC,
        0.044194173824159216f, nullptr);

    // 7) softmax -> bf16 P
    softmax_kernel<<<BATCH * HW, 256>>>();

    // 8) ao[i,c] = P[i,:] . V[c,:]   (bf16)
    mmb_kernel<0,1><<<dim3(CCH / 128, HW / 128, BATCH), 256, MMB_SMEM>>>(
        p, v, ao, HW, HW, HW, CCH, sSC, sXN, sXN, nullptr, nullptr, 0);

    // 9) out[o,i] = Wo[o,:] . ao[i,:] + bo + xn[o,i]   (bf16 MMA, fp32 out)
    mmb_kernel<3,0><<<dim3(HW / 128, CCH / 128, BATCH), 256, MMB_SMEM>>>(
        wob, ao, out, CCH, CCH, CCH, HW, 0, sXN, sXN, out_b, xn, sXN);
}

// round 14
// speedup vs baseline: 1.8482x; 1.2096x over previous
#include <cuda_runtime.h>
#include <cuda_bf16.h>
#include <cstdint>
#include <math.h>

#define BATCH 4
#define CCH   512
#define HW    4096
#define NGRP  32
#define CPG   16

// ---------------- scratch (device globals; no allocation) ----------------
__device__ float g_xn [(size_t)BATCH * CCH * HW];          // residual fp32 [b][c][i]
__device__ __nv_bfloat16 g_xnb[(size_t)BATCH * HW * CCH];  // bf16 [b][i][c]
__device__ __nv_bfloat16 g_q  [(size_t)BATCH * HW * CCH];  // bf16 [b][i][o]
__device__ __nv_bfloat16 g_k  [(size_t)BATCH * HW * CCH];  // bf16 [b][i][o]
__device__ __nv_bfloat16 g_v  [(size_t)BATCH * CCH * HW];  // bf16 [b][c][j]
__device__ float g_sc [(size_t)BATCH * HW * HW];           // fp32 scores 256MB
__device__ __nv_bfloat16 g_p  [(size_t)BATCH * HW * HW];   // bf16 probs 128MB
__device__ __nv_bfloat16 g_ao [(size_t)BATCH * HW * CCH];  // bf16 [b][i][c]
__device__ __nv_bfloat16 g_wb [(size_t)3 * CCH * CCH];     // bf16 [Wq;Wk;Wv]
__device__ __nv_bfloat16 g_wob[(size_t)CCH * CCH];         // bf16 Wo

// ---------------- helpers ----------------
__device__ __forceinline__ uint32_t smem_u32(const void* p) {
    uint32_t a;
    asm("{ .reg .u64 t; cvta.to.shared.u64 t, %1; cvt.u32.u64 %0, t; }" : "=r"(a) : "l"(p));
    return a;
}
__device__ __forceinline__ void cp_async16(uint32_t s, const void* g) {
    asm volatile("cp.async.cg.shared.global [%0], [%1], 16;" :: "r"(s), "l"(g));
}
#define CP_COMMIT() asm volatile("cp.async.commit_group;" ::: "memory")
#define CP_WAIT(N)  asm volatile("cp.async.wait_group %0;" :: "n"(N) : "memory")

__device__ __forceinline__ uint32_t pack_bf2(float lo, float hi) {
    __nv_bfloat162 h = __floats2bfloat162_rn(lo, hi);
    return *reinterpret_cast<uint32_t*>(&h);
}
__device__ __forceinline__ void ldmx4(uint32_t* r, uint32_t addr) {
    asm volatile("ldmatrix.sync.aligned.m8n8.x4.shared.b16 {%0,%1,%2,%3}, [%4];"
                 : "=r"(r[0]), "=r"(r[1]), "=r"(r[2]), "=r"(r[3]) : "r"(addr));
}
__device__ __forceinline__ void mma_bf16(float* d, const uint32_t* a, const uint32_t* b) {
    asm volatile(
        "mma.sync.aligned.m16n8k16.row.col.f32.bf16.bf16.f32 "
        "{%0,%1,%2,%3}, {%4,%5,%6,%7}, {%8,%9}, {%0,%1,%2,%3};"
        : "+f"(d[0]), "+f"(d[1]), "+f"(d[2]), "+f"(d[3])
        : "r"(a[0]), "r"(a[1]), "r"(a[2]), "r"(a[3]), "r"(b[0]), "r"(b[1]));
}

// ---------------- weight prep (convert to bf16, identity layout) ----------------
__global__ __launch_bounds__(256) void prep_wb_kernel(const float* __restrict__ src,
                                                      __nv_bfloat16* __restrict__ dst, int n) {
    int i = blockIdx.x * 256 + threadIdx.x;
    if (i < n) dst[i] = __float2bfloat16_rn(src[i]);
}

// ---------------- GroupNorm ----------------
__global__ __launch_bounds__(256) void gn_kernel(const float* __restrict__ x,
                                                 const float* __restrict__ w,
                                                 const float* __restrict__ bias) {
    int bg = blockIdx.x;
    int b = bg / NGRP, g = bg % NGRP;
    const size_t base = ((size_t)(b * CCH + g * CPG)) * HW;
    const float4* x4 = (const float4*)(x + base);
    float4* o4 = (float4*)(g_xn + base);
    int t = threadIdx.x;
    const int N4 = (CPG * HW) / 4;

    float s = 0.f, ss = 0.f;
    for (int i = t; i < N4; i += 256) {
        float4 v = x4[i];
        s  += v.x + v.y + v.z + v.w;
        ss += v.x * v.x + v.y * v.y + v.z * v.z + v.w * v.w;
    }
    __shared__ float sh0[256], sh1[256];
    sh0[t] = s; sh1[t] = ss;
    __syncthreads();
    for (int off = 128; off; off >>= 1) {
        if (t < off) { sh0[t] += sh0[t + off]; sh1[t] += sh1[t + off]; }
        __syncthreads();
    }
    const float inv = 1.f / (float)(CPG * HW);
    float mean = sh0[0] * inv;
    float var  = sh1[0] * inv - mean * mean;
    float rstd = rsqrtf(var + 1e-5f);

    for (int i = t; i < N4; i += 256) {
        int c = g * CPG + ((i * 4) >> 12);
        float sw = w[c] * rstd;
        float sb = bias[c] - mean * sw;
        float4 v = x4[i];
        float4 o;
        o.x = v.x * sw + sb; o.y = v.y * sw + sb;
        o.z = v.z * sw + sb; o.w = v.w * sw + sb;
        o4[i] = o;
    }
}

// ---------------- transpose -> xnb (bf16), identity cols ----------------
__global__ __launch_bounds__(256) void tr_kernel() {
    __shared__ float tile[32][33];
    int b = blockIdx.z;
    const float* in = g_xn + (size_t)b * CCH * HW;
    __nv_bfloat16* ob = g_xnb + (size_t)b * CCH * HW;
    int i0 = blockIdx.x * 32;
    int c0 = blockIdx.y * 32;
    int tx = threadIdx.x & 31, ty = threadIdx.x >> 5;
#pragma unroll
    for (int j = 0; j < 32; j += 8)
        tile[ty + j][tx] = in[(size_t)(c0 + ty + j) * HW + i0 + tx];
    __syncthreads();
    const int c = c0 + tx;
#pragma unroll
    for (int j = 0; j < 32; j += 8)
        ob[(size_t)(i0 + ty + j) * CCH + c] = __float2bfloat16_rn(tile[tx][ty + j]);
}

// ---------------- bf16 warp-MMA GEMM via ldmatrix (ALL GEMMs) ----------------
// D[m,n] = alpha * sum_k A[m,k]*B[n,k] (+ epilogue). Tile 128x128, K-slab 32,
// 8 warps (4m x 2n), warp 32x64.
// EPI: 0 = alpha only
//      1 = +bias[m]
//      2 = +bias[n], split bf16 output: n<512 -> Cv, n>=512 -> C2v (fused QK)
//      3 = +bias[m] + resid[m,n] (fp32 out)
// OUTBF: 1 = bf16 packed output, 0 = fp32 output
#define LDPB 20
#define TILEB_BYTES (128 * LDPB * 4)
#define MMB_SMEM (4 * TILEB_BYTES)

template<int EPI, int OUTBF>
__global__ __launch_bounds__(256, 2) void mmb_kernel(
    const __nv_bfloat16* __restrict__ A, const __nv_bfloat16* __restrict__ B,
    void* __restrict__ Cv, void* __restrict__ C2v,
    int Kd, int lda, int ldb, int ldc,
    size_t sA, size_t sB, size_t sC,
    float alpha, const float* __restrict__ bias,
    const float* __restrict__ resid, size_t sR)
{
    extern __shared__ uint32_t smu[];
    const uint32_t sbase = smem_u32(smu);

    const int t = threadIdx.x;
    const int lane = t & 31, wid = t >> 5;
    const int gid = lane >> 2, qid = lane & 3;
    const int wm = (wid & 3) * 32, wn = (wid >> 2) * 64;

    const int bz = blockIdx.z;
    const __nv_bfloat16* Ab = A + (size_t)bz * sA;
    const __nv_bfloat16* Bb = B + (size_t)bz * sB;
    const int m0 = blockIdx.y * 128;
    const int n0 = blockIdx.x * 128;

    const int lrow = t >> 2;
    const int lch  = t & 3;

    const int a_row  = wm + (lane & 15);
    const int a_uadd = (lane >> 4) << 2;            // u32 offset
    const int b_row  = wn + ((lane & 16) >> 1) + (lane & 7);
    const int b_uadd = (lane & 8) ? 4 : 0;

    float acc[2][8][4];
#pragma unroll
    for (int mi = 0; mi < 2; mi++)
#pragma unroll
        for (int ni = 0; ni < 8; ni++)
#pragma unroll
            for (int j = 0; j < 4; j++) acc[mi][ni][j] = 0.f;

    const int nslab = Kd >> 5;

    {
        const __nv_bfloat16* ga = Ab + (size_t)(m0 + lrow) * lda + lch * 8;
        const __nv_bfloat16* gb = Bb + (size_t)(n0 + lrow) * ldb + lch * 8;
        uint32_t da = sbase + (uint32_t)((lrow * LDPB + lch * 4) * 4);
        uint32_t db = da + 2u * TILEB_BYTES;
        cp_async16(da, ga);
        cp_async16(da + 64u * LDPB * 4u, ga + (size_t)64 * lda);
        cp_async16(db, gb);
        cp_async16(db + 64u * LDPB * 4u, gb + (size_t)64 * ldb);
        CP_COMMIT();
    }

    int buf = 0;
    for (int s = 0; s < nslab; s++) {
        if (s + 1 < nslab) {
            int k0 = (s + 1) << 5;
            int nb = buf ^ 1;
            const __nv_bfloat16* ga = Ab + (size_t)(m0 + lrow) * lda + k0 + lch * 8;
            const __nv_bfloat16* gb = Bb + (size_t)(n0 + lrow) * ldb + k0 + lch * 8;
            uint32_t da = sbase + (uint32_t)nb * TILEB_BYTES + (uint32_t)((lrow * LDPB + lch * 4) * 4);
            uint32_t db = da + 2u * TILEB_BYTES;
            cp_async16(da, ga);
            cp_async16(da + 64u * LDPB * 4u, ga + (size_t)64 * lda);
            cp_async16(db, gb);
            cp_async16(db + 64u * LDPB * 4u, gb + (size_t)64 * ldb);
            CP_COMMIT();
            CP_WAIT(1);
        } else {
            CP_WAIT(0);
        }
        __syncthreads();

        const uint32_t abase = sbase + (uint32_t)buf * TILEB_BYTES;
        const uint32_t bbase = abase + 2u * TILEB_BYTES;
#pragma unroll
        for (int s2 = 0; s2 < 2; s2++) {
            const int kb = s2 * 8;
            uint32_t afr[2][4];
#pragma unroll
            for (int mi = 0; mi < 2; mi++)
                ldmx4(afr[mi], abase + (uint32_t)(((a_row + mi * 16) * LDPB + kb + a_uadd) * 4));
            uint32_t bfr[8][2];
#pragma unroll
            for (int nj = 0; nj < 4; nj++) {
                uint32_t r[4];
                ldmx4(r, bbase + (uint32_t)(((b_row + nj * 16) * LDPB + kb + b_uadd) * 4));
                bfr[2 * nj][0] = r[0]; bfr[2 * nj][1] = r[1];
                bfr[2 * nj + 1][0] = r[2]; bfr[2 * nj + 1][1] = r[3];
            }
#pragma unroll
            for (int mi = 0; mi < 2; mi++)
#pragma unroll
                for (int ni = 0; ni < 8; ni++)
                    mma_bf16(acc[mi][ni], afr[mi], bfr[ni]);
        }
        __syncthreads();
        buf ^= 1;
    }

    // epilogue
#pragma unroll
    for (int mi = 0; mi < 2; mi++) {
        const int r0 = m0 + wm + mi * 16 + gid;
        const int r1 = r0 + 8;
        float b0 = 0.f, b1 = 0.f;
        if (EPI == 1 || EPI == 3) { b0 = bias[r0]; b1 = bias[r1]; }
#pragma unroll
        for (int ni = 0; ni < 8; ni++) {
            const int col = n0 + wn + ni * 8 + 2 * qid;
            float o00 = acc[mi][ni][0] * alpha, o01 = acc[mi][ni][1] * alpha;
            float o10 = acc[mi][ni][2] * alpha, o11 = acc[mi][ni][3] * alpha;
            if (EPI == 1 || EPI == 3) { o00 += b0; o01 += b0; o10 += b1; o11 += b1; }
            if (EPI == 2) {
                float bn0 = bias[col], bn1 = bias[col + 1];
                o00 += bn0; o01 += bn1; o10 += bn0; o11 += bn1;
            }
            if (EPI == 2) {
                // fused QK split: n<512 -> Cv (Q), n>=512 -> C2v (K); bf16 out
                uint32_t* Cb;
                int cp;
                if (col < 512) { Cb = (uint32_t*)Cv  + (size_t)bz * (sC >> 1); cp = col >> 1; }
                else           { Cb = (uint32_t*)C2v + (size_t)bz * (sC >> 1); cp = (col - 512) >> 1; }
                Cb[(size_t)r0 * (ldc >> 1) + cp] = pack_bf2(o00, o01);
                Cb[(size_t)r1 * (ldc >> 1) + cp] = pack_bf2(o10, o11);
            } else if (OUTBF) {
                uint32_t* Cb = (uint32_t*)Cv + (size_t)bz * (sC >> 1);
                const int cp = col >> 1;
                Cb[(size_t)r0 * (ldc >> 1) + cp] = pack_bf2(o00, o01);
                Cb[(size_t)r1 * (ldc >> 1) + cp] = pack_bf2(o10, o11);
            } else {
                float* Cb = (float*)Cv + (size_t)bz * sC;
                if (EPI == 3) {
                    const float* rb = resid + (size_t)bz * sR;
                    float2 rv0 = *(const float2*)(rb + (size_t)r0 * ldc + col);
                    float2 rv1 = *(const float2*)(rb + (size_t)r1 * ldc + col);
                    o00 += rv0.x; o01 += rv0.y; o10 += rv1.x; o11 += rv1.y;
                }
                *(float2*)(Cb + (size_t)r0 * ldc + col) = make_float2(o00, o01);
                *(float2*)(Cb + (size_t)r1 * ldc + col) = make_float2(o10, o11);
            }
        }
    }
}

// ---------------- row softmax: fp32 g_sc -> bf16 g_p ----------------
__global__ __launch_bounds__(256) void softmax_kernel() {
    const float4* row = (const float4*)(g_sc + (size_t)blockIdx.x * HW);
    uint2* prow = (uint2*)(g_p + (size_t)blockIdx.x * HW);
    int t = threadIdx.x;
    float4 v[4];
    float mx = -1e30f;
#pragma unroll
    for (int i = 0; i < 4; i++) {
        v[i] = row[t + i * 256];
        mx = fmaxf(mx, fmaxf(fmaxf(v[i].x, v[i].y), fmaxf(v[i].z, v[i].w)));
    }
    __shared__ float sh[8];
#pragma unroll
    for (int o = 16; o; o >>= 1) mx = fmaxf(mx, __shfl_xor_sync(0xffffffffu, mx, o));
    if ((t & 31) == 0) sh[t >> 5] = mx;
    __syncthreads();
    mx = sh[0];
#pragma unroll
    for (int i = 1; i < 8; i++) mx = fmaxf(mx, sh[i]);

    float s = 0.f;
#pragma unroll
    for (int i = 0; i < 4; i++) {
        v[i].x = __expf(v[i].x - mx); v[i].y = __expf(v[i].y - mx);
        v[i].z = __expf(v[i].z - mx); v[i].w = __expf(v[i].w - mx);
        s += v[i].x + v[i].y + v[i].z + v[i].w;
    }
#pragma unroll
    for (int o = 16; o; o >>= 1) s += __shfl_xor_sync(0xffffffffu, s, o);
    __syncthreads();
    if ((t & 31) == 0) sh[t >> 5] = s;
    __syncthreads();
    s = 0.f;
#pragma unroll
    for (int i = 0; i < 8; i++) s += sh[i];
    float inv = 1.f / s;
#pragma unroll
    for (int i = 0; i < 4; i++) {
        uint2 o;
        o.x = pack_bf2(v[i].x * inv, v[i].y * inv);
        o.y = pack_bf2(v[i].z * inv, v[i].w * inv);
        prow[t + i * 256] = o;
    }
}

// ---------------- launch ----------------
extern "C" void kernel_launch(void* const* d_in, const int* in_sizes, int n_in,
                              void* d_out, int out_size) {
    const float* x     = (const float*)d_in[0];
    const float* gn_w  = (const float*)d_in[1];
    const float* gn_b  = (const float*)d_in[2];
    const float* qkv_w = (const float*)d_in[3];
    const float* qkv_b = (const float*)d_in[4];
    const float* out_w = (const float*)d_in[5];
    const float* out_b = (const float*)d_in[6];
    float* out = (float*)d_out;

    float *xn, *sc;
    __nv_bfloat16 *xnb, *q, *k, *v, *p, *ao, *wb, *wob;
    cudaGetSymbolAddress((void**)&xn,  g_xn);
    cudaGetSymbolAddress((void**)&xnb, g_xnb);
    cudaGetSymbolAddress((void**)&q,   g_q);
    cudaGetSymbolAddress((void**)&k,   g_k);
    cudaGetSymbolAddress((void**)&v,   g_v);
    cudaGetSymbolAddress((void**)&sc,  g_sc);
    cudaGetSymbolAddress((void**)&p,   g_p);
    cudaGetSymbolAddress((void**)&ao,  g_ao);
    cudaGetSymbolAddress((void**)&wb,  g_wb);
    cudaGetSymbolAddress((void**)&wob, g_wob);

    cudaFuncSetAttribute(mmb_kernel<2,1>, cudaFuncAttributeMaxDynamicSharedMemorySize, MMB_SMEM);
    cudaFuncSetAttribute(mmb_kernel<1,1>, cudaFuncAttributeMaxDynamicSharedMemorySize, MMB_SMEM);
    cudaFuncSetAttribute(mmb_kernel<0,0>, cudaFuncAttributeMaxDynamicSharedMemorySize, MMB_SMEM);
    cudaFuncSetAttribute(mmb_kernel<0,1>, cudaFuncAttributeMaxDynamicSharedMemorySize, MMB_SMEM);
    cudaFuncSetAttribute(mmb_kernel<3,0>, cudaFuncAttributeMaxDynamicSharedMemorySize, MMB_SMEM);

    const size_t sXN = (size_t)CCH * HW;
    const size_t sSC = (size_t)HW * HW;

    // 0) weight prep (all bf16)
    prep_wb_kernel<<<(3 * CCH * CCH + 255) / 256, 256>>>(qkv_w, wb, 3 * CCH * CCH);
    prep_wb_kernel<<<(CCH * CCH + 255) / 256, 256>>>(out_w, wob, CCH * CCH);

    // 1) GroupNorm
    gn_kernel<<<BATCH * NGRP, 256>>>(x, gn_w, gn_b);
    // 2) transpose -> xnb (bf16)
    tr_kernel<<<dim3(HW / 32, CCH / 32, BATCH), 256>>>();

    // 3) fused Q,K projection: N=1024 over [Wq;Wk], bias[n], split bf16 out
    mmb_kernel<2,1><<<dim3(1024 / 128, HW / 128, BATCH), 256, MMB_SMEM>>>(
        xnb, wb, q, k, CCH, CCH, CCH, CCH, sXN, 0, sXN, 1.f, qkv_b, nullptr, 0);

    // 4) V[c,j] = Wv[c,:] . xn[:,j] + bv
    mmb_kernel<1,1><<<dim3(HW / 128, CCH / 128, BATCH), 256, MMB_SMEM>>>(
        wb + (size_t)2 * CCH * CCH, xnb, v, nullptr, CCH, CCH, CCH, HW, 0, sXN, sXN,
        1.f, qkv_b + 2 * CCH, nullptr, 0);

    // 5) scores[i,j] = scale * Q[i,:].K[j,:]  (bf16 MMA, fp32 out)
    mmb_kernel<0,0><<<dim3(HW / 128, HW / 128, BATCH), 256, MMB_SMEM>>>(
        q, k, sc, nullptr, CCH, CCH, CCH, HW, sXN, sXN, sSC,
        0.044194173824159216f, nullptr, nullptr, 0);

    // 6) softmax -> bf16 P
    softmax_kernel<<<BATCH * HW, 256>>>();

    // 7) ao[i,c] = P[i,:] . V[c,:]
    mmb_kernel<0,1><<<dim3(CCH / 128, HW / 128, BATCH), 256, MMB_SMEM>>>(
        p, v, ao, nullptr, HW, HW, HW, CCH, sSC, sXN, sXN, 1.f, nullptr, nullptr, 0);

    // 8) out[o,i] = Wo[o,:] . ao[i,:] + bo + xn[o,i]
    mmb_kernel<3,0><<<dim3(HW / 128, CCH / 128, BATCH), 256, MMB_SMEM>>>(
        wob, ao, out, nullptr, CCH, CCH, CCH, HW, 0, sXN, sXN, 1.f, out_b, xn, sXN);
}

// round 15
// speedup vs baseline: 1.8882x; 1.0217x over previous
#include <cuda_runtime.h>
#include <cuda_bf16.h>
#include <cstdint>
#include <math.h>

#define BATCH 4
#define CCH   512
#define HW    4096
#define NGRP  32
#define CPG   16

// ---------------- scratch (device globals; no allocation) ----------------
__device__ float g_xn [(size_t)BATCH * CCH * HW];          // residual fp32 [b][c][i]
__device__ __nv_bfloat16 g_xnb[(size_t)BATCH * HW * CCH];  // bf16 [b][i][c]
__device__ __nv_bfloat16 g_q  [(size_t)BATCH * HW * CCH];  // bf16 [b][i][o]
__device__ __nv_bfloat16 g_k  [(size_t)BATCH * HW * CCH];  // bf16 [b][i][o]
__device__ __nv_bfloat16 g_v  [(size_t)BATCH * CCH * HW];  // bf16 [b][c][j]
__device__ __nv_bfloat16 g_p  [(size_t)BATCH * HW * HW];   // bf16 scores->probs 128MB
__device__ __nv_bfloat16 g_ao [(size_t)BATCH * HW * CCH];  // bf16 [b][i][c]
__device__ __nv_bfloat16 g_wb [(size_t)3 * CCH * CCH];     // bf16 [Wq;Wk;Wv]
__device__ __nv_bfloat16 g_wob[(size_t)CCH * CCH];         // bf16 Wo

// ---------------- helpers ----------------
__device__ __forceinline__ uint32_t smem_u32(const void* p) {
    uint32_t a;
    asm("{ .reg .u64 t; cvta.to.shared.u64 t, %1; cvt.u32.u64 %0, t; }" : "=r"(a) : "l"(p));
    return a;
}
__device__ __forceinline__ void cp_async16(uint32_t s, const void* g) {
    asm volatile("cp.async.cg.shared.global [%0], [%1], 16;" :: "r"(s), "l"(g));
}
#define CP_COMMIT() asm volatile("cp.async.commit_group;" ::: "memory")
#define CP_WAIT(N)  asm volatile("cp.async.wait_group %0;" :: "n"(N) : "memory")

__device__ __forceinline__ uint32_t pack_bf2(float lo, float hi) {
    __nv_bfloat162 h = __floats2bfloat162_rn(lo, hi);
    return *reinterpret_cast<uint32_t*>(&h);
}
__device__ __forceinline__ float2 unpack_bf2(uint32_t u) {
    __nv_bfloat162 h = *reinterpret_cast<__nv_bfloat162*>(&u);
    return __bfloat1622float2(h);
}
__device__ __forceinline__ void ldmx4(uint32_t* r, uint32_t addr) {
    asm volatile("ldmatrix.sync.aligned.m8n8.x4.shared.b16 {%0,%1,%2,%3}, [%4];"
                 : "=r"(r[0]), "=r"(r[1]), "=r"(r[2]), "=r"(r[3]) : "r"(addr));
}
__device__ __forceinline__ void mma_bf16(float* d, const uint32_t* a, const uint32_t* b) {
    asm volatile(
        "mma.sync.aligned.m16n8k16.row.col.f32.bf16.bf16.f32 "
        "{%0,%1,%2,%3}, {%4,%5,%6,%7}, {%8,%9}, {%0,%1,%2,%3};"
        : "+f"(d[0]), "+f"(d[1]), "+f"(d[2]), "+f"(d[3])
        : "r"(a[0]), "r"(a[1]), "r"(a[2]), "r"(a[3]), "r"(b[0]), "r"(b[1]));
}

// ---------------- weight prep (convert to bf16, identity layout) ----------------
__global__ __launch_bounds__(256) void prep_wb_kernel(const float* __restrict__ src,
                                                      __nv_bfloat16* __restrict__ dst, int n) {
    int i = blockIdx.x * 256 + threadIdx.x;
    if (i < n) dst[i] = __float2bfloat16_rn(src[i]);
}

// ---------------- GroupNorm ----------------
__global__ __launch_bounds__(256) void gn_kernel(const float* __restrict__ x,
                                                 const float* __restrict__ w,
                                                 const float* __restrict__ bias) {
    int bg = blockIdx.x;
    int b = bg / NGRP, g = bg % NGRP;
    const size_t base = ((size_t)(b * CCH + g * CPG)) * HW;
    const float4* x4 = (const float4*)(x + base);
    float4* o4 = (float4*)(g_xn + base);
    int t = threadIdx.x;
    const int N4 = (CPG * HW) / 4;

    float s = 0.f, ss = 0.f;
    for (int i = t; i < N4; i += 256) {
        float4 v = x4[i];
        s  += v.x + v.y + v.z + v.w;
        ss += v.x * v.x + v.y * v.y + v.z * v.z + v.w * v.w;
    }
    __shared__ float sh0[256], sh1[256];
    sh0[t] = s; sh1[t] = ss;
    __syncthreads();
    for (int off = 128; off; off >>= 1) {
        if (t < off) { sh0[t] += sh0[t + off]; sh1[t] += sh1[t + off]; }
        __syncthreads();
    }
    const float inv = 1.f / (float)(CPG * HW);
    float mean = sh0[0] * inv;
    float var  = sh1[0] * inv - mean * mean;
    float rstd = rsqrtf(var + 1e-5f);

    for (int i = t; i < N4; i += 256) {
        int c = g * CPG + ((i * 4) >> 12);
        float sw = w[c] * rstd;
        float sb = bias[c] - mean * sw;
        float4 v = x4[i];
        float4 o;
        o.x = v.x * sw + sb; o.y = v.y * sw + sb;
        o.z = v.z * sw + sb; o.w = v.w * sw + sb;
        o4[i] = o;
    }
}

// ---------------- transpose -> xnb (bf16), identity cols ----------------
__global__ __launch_bounds__(256) void tr_kernel() {
    __shared__ float tile[32][33];
    int b = blockIdx.z;
    const float* in = g_xn + (size_t)b * CCH * HW;
    __nv_bfloat16* ob = g_xnb + (size_t)b * CCH * HW;
    int i0 = blockIdx.x * 32;
    int c0 = blockIdx.y * 32;
    int tx = threadIdx.x & 31, ty = threadIdx.x >> 5;
#pragma unroll
    for (int j = 0; j < 32; j += 8)
        tile[ty + j][tx] = in[(size_t)(c0 + ty + j) * HW + i0 + tx];
    __syncthreads();
    const int c = c0 + tx;
#pragma unroll
    for (int j = 0; j < 32; j += 8)
        ob[(size_t)(i0 + ty + j) * CCH + c] = __float2bfloat16_rn(tile[tx][ty + j]);
}

// ---------------- bf16 warp-MMA GEMM via ldmatrix (ALL GEMMs) ----------------
// D[m,n] = alpha * sum_k A[m,k]*B[n,k] (+ epilogue). Tile 128x128, K-slab 32,
// 8 warps (4m x 2n), warp 32x64.
// EPI: 0 = alpha only
//      1 = +bias[m]
//      2 = +bias[n], split bf16 output: n<512 -> Cv, n>=512 -> C2v (fused QK)
//      3 = +bias[m] + resid[m,n] (fp32 out)
// OUTBF: 1 = bf16 packed output, 0 = fp32 output
#define LDPB 20
#define TILEB_BYTES (128 * LDPB * 4)
#define MMB_SMEM (4 * TILEB_BYTES)

template<int EPI, int OUTBF>
__global__ __launch_bounds__(256, 2) void mmb_kernel(
    const __nv_bfloat16* __restrict__ A, const __nv_bfloat16* __restrict__ B,
    void* __restrict__ Cv, void* __restrict__ C2v,
    int Kd, int lda, int ldb, int ldc,
    size_t sA, size_t sB, size_t sC,
    float alpha, const float* __restrict__ bias,
    const float* __restrict__ resid, size_t sR)
{
    extern __shared__ uint32_t smu[];
    const uint32_t sbase = smem_u32(smu);

    const int t = threadIdx.x;
    const int lane = t & 31, wid = t >> 5;
    const int gid = lane >> 2, qid = lane & 3;
    const int wm = (wid & 3) * 32, wn = (wid >> 2) * 64;

    const int bz = blockIdx.z;
    const __nv_bfloat16* Ab = A + (size_t)bz * sA;
    const __nv_bfloat16* Bb = B + (size_t)bz * sB;
    const int m0 = blockIdx.y * 128;
    const int n0 = blockIdx.x * 128;

    const int lrow = t >> 2;
    const int lch  = t & 3;

    const int a_row  = wm + (lane & 15);
    const int a_uadd = (lane >> 4) << 2;            // u32 offset
    const int b_row  = wn + ((lane & 16) >> 1) + (lane & 7);
    const int b_uadd = (lane & 8) ? 4 : 0;

    float acc[2][8][4];
#pragma unroll
    for (int mi = 0; mi < 2; mi++)
#pragma unroll
        for (int ni = 0; ni < 8; ni++)
#pragma unroll
            for (int j = 0; j < 4; j++) acc[mi][ni][j] = 0.f;

    const int nslab = Kd >> 5;

    {
        const __nv_bfloat16* ga = Ab + (size_t)(m0 + lrow) * lda + lch * 8;
        const __nv_bfloat16* gb = Bb + (size_t)(n0 + lrow) * ldb + lch * 8;
        uint32_t da = sbase + (uint32_t)((lrow * LDPB + lch * 4) * 4);
        uint32_t db = da + 2u * TILEB_BYTES;
        cp_async16(da, ga);
        cp_async16(da + 64u * LDPB * 4u, ga + (size_t)64 * lda);
        cp_async16(db, gb);
        cp_async16(db + 64u * LDPB * 4u, gb + (size_t)64 * ldb);
        CP_COMMIT();
    }

    int buf = 0;
    for (int s = 0; s < nslab; s++) {
        if (s + 1 < nslab) {
            int k0 = (s + 1) << 5;
            int nb = buf ^ 1;
            const __nv_bfloat16* ga = Ab + (size_t)(m0 + lrow) * lda + k0 + lch * 8;
            const __nv_bfloat16* gb = Bb + (size_t)(n0 + lrow) * ldb + k0 + lch * 8;
            uint32_t da = sbase + (uint32_t)nb * TILEB_BYTES + (uint32_t)((lrow * LDPB + lch * 4) * 4);
            uint32_t db = da + 2u * TILEB_BYTES;
            cp_async16(da, ga);
            cp_async16(da + 64u * LDPB * 4u, ga + (size_t)64 * lda);
            cp_async16(db, gb);
            cp_async16(db + 64u * LDPB * 4u, gb + (size_t)64 * ldb);
            CP_COMMIT();
            CP_WAIT(1);
        } else {
            CP_WAIT(0);
        }
        __syncthreads();

        const uint32_t abase = sbase + (uint32_t)buf * TILEB_BYTES;
        const uint32_t bbase = abase + 2u * TILEB_BYTES;
#pragma unroll
        for (int s2 = 0; s2 < 2; s2++) {
            const int kb = s2 * 8;
            uint32_t afr[2][4];
#pragma unroll
            for (int mi = 0; mi < 2; mi++)
                ldmx4(afr[mi], abase + (uint32_t)(((a_row + mi * 16) * LDPB + kb + a_uadd) * 4));
            uint32_t bfr[8][2];
#pragma unroll
            for (int nj = 0; nj < 4; nj++) {
                uint32_t r[4];
                ldmx4(r, bbase + (uint32_t)(((b_row + nj * 16) * LDPB + kb + b_uadd) * 4));
                bfr[2 * nj][0] = r[0]; bfr[2 * nj][1] = r[1];
                bfr[2 * nj + 1][0] = r[2]; bfr[2 * nj + 1][1] = r[3];
            }
#pragma unroll
            for (int mi = 0; mi < 2; mi++)
#pragma unroll
                for (int ni = 0; ni < 8; ni++)
                    mma_bf16(acc[mi][ni], afr[mi], bfr[ni]);
        }
        __syncthreads();
        buf ^= 1;
    }

    // epilogue
#pragma unroll
    for (int mi = 0; mi < 2; mi++) {
        const int r0 = m0 + wm + mi * 16 + gid;
        const int r1 = r0 + 8;
        float b0 = 0.f, b1 = 0.f;
        if (EPI == 1 || EPI == 3) { b0 = bias[r0]; b1 = bias[r1]; }
#pragma unroll
        for (int ni = 0; ni < 8; ni++) {
            const int col = n0 + wn + ni * 8 + 2 * qid;
            float o00 = acc[mi][ni][0] * alpha, o01 = acc[mi][ni][1] * alpha;
            float o10 = acc[mi][ni][2] * alpha, o11 = acc[mi][ni][3] * alpha;
            if (EPI == 1 || EPI == 3) { o00 += b0; o01 += b0; o10 += b1; o11 += b1; }
            if (EPI == 2) {
                float bn0 = bias[col], bn1 = bias[col + 1];
                o00 += bn0; o01 += bn1; o10 += bn0; o11 += bn1;
            }
            if (EPI == 2) {
                // fused QK split: n<512 -> Cv (Q), n>=512 -> C2v (K); bf16 out
                uint32_t* Cb;
                int cp;
                if (col < 512) { Cb = (uint32_t*)Cv  + (size_t)bz * (sC >> 1); cp = col >> 1; }
                else           { Cb = (uint32_t*)C2v + (size_t)bz * (sC >> 1); cp = (col - 512) >> 1; }
                Cb[(size_t)r0 * (ldc >> 1) + cp] = pack_bf2(o00, o01);
                Cb[(size_t)r1 * (ldc >> 1) + cp] = pack_bf2(o10, o11);
            } else if (OUTBF) {
                uint32_t* Cb = (uint32_t*)Cv + (size_t)bz * (sC >> 1);
                const int cp = col >> 1;
                Cb[(size_t)r0 * (ldc >> 1) + cp] = pack_bf2(o00, o01);
                Cb[(size_t)r1 * (ldc >> 1) + cp] = pack_bf2(o10, o11);
            } else {
                float* Cb = (float*)Cv + (size_t)bz * sC;
                if (EPI == 3) {
                    const float* rb = resid + (size_t)bz * sR;
                    float2 rv0 = *(const float2*)(rb + (size_t)r0 * ldc + col);
                    float2 rv1 = *(const float2*)(rb + (size_t)r1 * ldc + col);
                    o00 += rv0.x; o01 += rv0.y; o10 += rv1.x; o11 += rv1.y;
                }
                *(float2*)(Cb + (size_t)r0 * ldc + col) = make_float2(o00, o01);
                *(float2*)(Cb + (size_t)r1 * ldc + col) = make_float2(o10, o11);
            }
        }
    }
}

// ---------------- row softmax: bf16 g_p -> bf16 g_p (in place, fp32 math) ----------------
// Row = 4096 bf16 = 512 uint4. 256 threads, 2 uint4 (16 values) per thread.
__global__ __launch_bounds__(256) void softmax_kernel() {
    uint4* row = (uint4*)(g_p + (size_t)blockIdx.x * HW);
    int t = threadIdx.x;
    uint4 u[2];
    float f[2][8];
    float mx = -1e30f;
#pragma unroll
    for (int i = 0; i < 2; i++) {
        u[i] = row[t + i * 256];
        float2 a0 = unpack_bf2(u[i].x), a1 = unpack_bf2(u[i].y);
        float2 a2 = unpack_bf2(u[i].z), a3 = unpack_bf2(u[i].w);
        f[i][0] = a0.x; f[i][1] = a0.y; f[i][2] = a1.x; f[i][3] = a1.y;
        f[i][4] = a2.x; f[i][5] = a2.y; f[i][6] = a3.x; f[i][7] = a3.y;
#pragma unroll
        for (int j = 0; j < 8; j++) mx = fmaxf(mx, f[i][j]);
    }
    __shared__ float sh[8];
#pragma unroll
    for (int o = 16; o; o >>= 1) mx = fmaxf(mx, __shfl_xor_sync(0xffffffffu, mx, o));
    if ((t & 31) == 0) sh[t >> 5] = mx;
    __syncthreads();
    mx = sh[0];
#pragma unroll
    for (int i = 1; i < 8; i++) mx = fmaxf(mx, sh[i]);

    float s = 0.f;
#pragma unroll
    for (int i = 0; i < 2; i++)
#pragma unroll
        for (int j = 0; j < 8; j++) {
            f[i][j] = __expf(f[i][j] - mx);
            s += f[i][j];
        }
#pragma unroll
    for (int o = 16; o; o >>= 1) s += __shfl_xor_sync(0xffffffffu, s, o);
    __syncthreads();
    if ((t & 31) == 0) sh[t >> 5] = s;
    __syncthreads();
    s = 0.f;
#pragma unroll
    for (int i = 0; i < 8; i++) s += sh[i];
    float inv = 1.f / s;
#pragma unroll
    for (int i = 0; i < 2; i++) {
        uint4 o;
        o.x = pack_bf2(f[i][0] * inv, f[i][1] * inv);
        o.y = pack_bf2(f[i][2] * inv, f[i][3] * inv);
        o.z = pack_bf2(f[i][4] * inv, f[i][5] * inv);
        o.w = pack_bf2(f[i][6] * inv, f[i][7] * inv);
        row[t + i * 256] = o;
    }
}

// ---------------- launch ----------------
extern "C" void kernel_launch(void* const* d_in, const int* in_sizes, int n_in,
                              void* d_out, int out_size) {
    const float* x     = (const float*)d_in[0];
    const float* gn_w  = (const float*)d_in[1];
    const float* gn_b  = (const float*)d_in[2];
    const float* qkv_w = (const float*)d_in[3];
    const float* qkv_b = (const float*)d_in[4];
    const float* out_w = (const float*)d_in[5];
    const float* out_b = (const float*)d_in[6];
    float* out = (float*)d_out;

    float *xn;
    __nv_bfloat16 *xnb, *q, *k, *v, *p, *ao, *wb, *wob;
    cudaGetSymbolAddress((void**)&xn,  g_xn);
    cudaGetSymbolAddress((void**)&xnb, g_xnb);
    cudaGetSymbolAddress((void**)&q,   g_q);
    cudaGetSymbolAddress((void**)&k,   g_k);
    cudaGetSymbolAddress((void**)&v,   g_v);
    cudaGetSymbolAddress((void**)&p,   g_p);
    cudaGetSymbolAddress((void**)&ao,  g_ao);
    cudaGetSymbolAddress((void**)&wb,  g_wb);
    cudaGetSymbolAddress((void**)&wob, g_wob);

    cudaFuncSetAttribute(mmb_kernel<2,1>, cudaFuncAttributeMaxDynamicSharedMemorySize, MMB_SMEM);
    cudaFuncSetAttribute(mmb_kernel<1,1>, cudaFuncAttributeMaxDynamicSharedMemorySize, MMB_SMEM);
    cudaFuncSetAttribute(mmb_kernel<0,1>, cudaFuncAttributeMaxDynamicSharedMemorySize, MMB_SMEM);
    cudaFuncSetAttribute(mmb_kernel<3,0>, cudaFuncAttributeMaxDynamicSharedMemorySize, MMB_SMEM);

    const size_t sXN = (size_t)CCH * HW;
    const size_t sSC = (size_t)HW * HW;

    // 0) weight prep (all bf16)
    prep_wb_kernel<<<(3 * CCH * CCH + 255) / 256, 256>>>(qkv_w, wb, 3 * CCH * CCH);
    prep_wb_kernel<<<(CCH * CCH + 255) / 256, 256>>>(out_w, wob, CCH * CCH);

    // 1) GroupNorm
    gn_kernel<<<BATCH * NGRP, 256>>>(x, gn_w, gn_b);
    // 2) transpose -> xnb (bf16)
    tr_kernel<<<dim3(HW / 32, CCH / 32, BATCH), 256>>>();

    // 3) fused Q,K projection: N=1024 over [Wq;Wk], bias[n], split bf16 out
    mmb_kernel<2,1><<<dim3(1024 / 128, HW / 128, BATCH), 256, MMB_SMEM>>>(
        xnb, wb, q, k, CCH, CCH, CCH, CCH, sXN, 0, sXN, 1.f, qkv_b, nullptr, 0);

    // 4) V[c,j] = Wv[c,:] . xn[:,j] + bv
    mmb_kernel<1,1><<<dim3(HW / 128, CCH / 128, BATCH), 256, MMB_SMEM>>>(
        wb + (size_t)2 * CCH * CCH, xnb, v, nullptr, CCH, CCH, CCH, HW, 0, sXN, sXN,
        1.f, qkv_b + 2 * CCH, nullptr, 0);

    // 5) scores[i,j] = scale * Q[i,:].K[j,:]  (bf16 MMA, bf16 out DIRECTLY to g_p)
    mmb_kernel<0,1><<<dim3(HW / 128, HW / 128, BATCH), 256, MMB_SMEM>>>(
        q, k, p, nullptr, CCH, CCH, CCH, HW, sXN, sXN, sSC,
        0.044194173824159216f, nullptr, nullptr, 0);

    // 6) softmax in-place on bf16 g_p
    softmax_kernel<<<BATCH * HW, 256>>>();

    // 7) ao[i,c] = P[i,:] . V[c,:]
    mmb_kernel<0,1><<<dim3(CCH / 128, HW / 128, BATCH), 256, MMB_SMEM>>>(
        p, v, ao, nullptr, HW, HW, HW, CCH, sSC, sXN, sXN, 1.f, nullptr, nullptr, 0);

    // 8) out[o,i] = Wo[o,:] . ao[i,:] + bo + xn[o,i]
    mmb_kernel<3,0><<<dim3(HW / 128, CCH / 128, BATCH), 256, MMB_SMEM>>>(
        wob, ao, out, nullptr, CCH, CCH, CCH, HW, 0, sXN, sXN, 1.f, out_b, xn, sXN);
}

// round 16
// speedup vs baseline: 2.0432x; 1.0821x over previous
#include <cuda_runtime.h>
#include <cuda_bf16.h>
#include <cstdint>
#include <math.h>

#define BATCH 4
#define CCH   512
#define HW    4096
#define NGRP  32
#define CPG   16

// ---------------- scratch (device globals; no allocation) ----------------
__device__ float g_xn [(size_t)BATCH * CCH * HW];          // residual fp32 [b][c][i]
__device__ __nv_bfloat16 g_xnb[(size_t)BATCH * HW * CCH];  // bf16 [b][i][c]
__device__ __nv_bfloat16 g_q  [(size_t)BATCH * HW * CCH];  // bf16 [b][i][o]
__device__ __nv_bfloat16 g_k  [(size_t)BATCH * HW * CCH];  // bf16 [b][i][o]
__device__ __nv_bfloat16 g_v  [(size_t)BATCH * CCH * HW];  // bf16 [b][c][j]
__device__ __nv_bfloat16 g_p  [(size_t)BATCH * HW * HW];   // bf16 scores->probs 128MB
__device__ __nv_bfloat16 g_ao [(size_t)BATCH * HW * CCH];  // bf16 [b][i][c]
__device__ __nv_bfloat16 g_wb [(size_t)3 * CCH * CCH];     // bf16 [Wq;Wk;Wv]
__device__ __nv_bfloat16 g_wob[(size_t)CCH * CCH];         // bf16 Wo

// ---------------- helpers ----------------
__device__ __forceinline__ uint32_t smem_u32(const void* p) {
    uint32_t a;
    asm("{ .reg .u64 t; cvta.to.shared.u64 t, %1; cvt.u32.u64 %0, t; }" : "=r"(a) : "l"(p));
    return a;
}
__device__ __forceinline__ void cp_async16(uint32_t s, const void* g) {
    asm volatile("cp.async.cg.shared.global [%0], [%1], 16;" :: "r"(s), "l"(g));
}
#define CP_COMMIT() asm volatile("cp.async.commit_group;" ::: "memory")
#define CP_WAIT(N)  asm volatile("cp.async.wait_group %0;" :: "n"(N) : "memory")

__device__ __forceinline__ uint32_t pack_bf2(float lo, float hi) {
    __nv_bfloat162 h = __floats2bfloat162_rn(lo, hi);
    return *reinterpret_cast<uint32_t*>(&h);
}
__device__ __forceinline__ float2 unpack_bf2(uint32_t u) {
    __nv_bfloat162 h = *reinterpret_cast<__nv_bfloat162*>(&u);
    return __bfloat1622float2(h);
}
__device__ __forceinline__ void ldmx4(uint32_t* r, uint32_t addr) {
    asm volatile("ldmatrix.sync.aligned.m8n8.x4.shared.b16 {%0,%1,%2,%3}, [%4];"
                 : "=r"(r[0]), "=r"(r[1]), "=r"(r[2]), "=r"(r[3]) : "r"(addr));
}
__device__ __forceinline__ void mma_bf16(float* d, const uint32_t* a, const uint32_t* b) {
    asm volatile(
        "mma.sync.aligned.m16n8k16.row.col.f32.bf16.bf16.f32 "
        "{%0,%1,%2,%3}, {%4,%5,%6,%7}, {%8,%9}, {%0,%1,%2,%3};"
        : "+f"(d[0]), "+f"(d[1]), "+f"(d[2]), "+f"(d[3])
        : "r"(a[0]), "r"(a[1]), "r"(a[2]), "r"(a[3]), "r"(b[0]), "r"(b[1]));
}

// ---------------- weight prep (convert to bf16, identity layout) ----------------
__global__ __launch_bounds__(256) void prep_wb_kernel(const float* __restrict__ src,
                                                      __nv_bfloat16* __restrict__ dst, int n) {
    int i = blockIdx.x * 256 + threadIdx.x;
    if (i < n) dst[i] = __float2bfloat16_rn(src[i]);
}

// ---------------- GroupNorm ----------------
__global__ __launch_bounds__(256) void gn_kernel(const float* __restrict__ x,
                                                 const float* __restrict__ w,
                                                 const float* __restrict__ bias) {
    int bg = blockIdx.x;
    int b = bg / NGRP, g = bg % NGRP;
    const size_t base = ((size_t)(b * CCH + g * CPG)) * HW;
    const float4* x4 = (const float4*)(x + base);
    float4* o4 = (float4*)(g_xn + base);
    int t = threadIdx.x;
    const int N4 = (CPG * HW) / 4;

    float s = 0.f, ss = 0.f;
    for (int i = t; i < N4; i += 256) {
        float4 v = x4[i];
        s  += v.x + v.y + v.z + v.w;
        ss += v.x * v.x + v.y * v.y + v.z * v.z + v.w * v.w;
    }
    __shared__ float sh0[256], sh1[256];
    sh0[t] = s; sh1[t] = ss;
    __syncthreads();
    for (int off = 128; off; off >>= 1) {
        if (t < off) { sh0[t] += sh0[t + off]; sh1[t] += sh1[t + off]; }
        __syncthreads();
    }
    const float inv = 1.f / (float)(CPG * HW);
    float mean = sh0[0] * inv;
    float var  = sh1[0] * inv - mean * mean;
    float rstd = rsqrtf(var + 1e-5f);

    for (int i = t; i < N4; i += 256) {
        int c = g * CPG + ((i * 4) >> 12);
        float sw = w[c] * rstd;
        float sb = bias[c] - mean * sw;
        float4 v = x4[i];
        float4 o;
        o.x = v.x * sw + sb; o.y = v.y * sw + sb;
        o.z = v.z * sw + sb; o.w = v.w * sw + sb;
        o4[i] = o;
    }
}

// ---------------- transpose -> xnb (bf16), identity cols ----------------
__global__ __launch_bounds__(256) void tr_kernel() {
    __shared__ float tile[32][33];
    int b = blockIdx.z;
    const float* in = g_xn + (size_t)b * CCH * HW;
    __nv_bfloat16* ob = g_xnb + (size_t)b * CCH * HW;
    int i0 = blockIdx.x * 32;
    int c0 = blockIdx.y * 32;
    int tx = threadIdx.x & 31, ty = threadIdx.x >> 5;
#pragma unroll
    for (int j = 0; j < 32; j += 8)
        tile[ty + j][tx] = in[(size_t)(c0 + ty + j) * HW + i0 + tx];
    __syncthreads();
    const int c = c0 + tx;
#pragma unroll
    for (int j = 0; j < 32; j += 8)
        ob[(size_t)(i0 + ty + j) * CCH + c] = __float2bfloat16_rn(tile[tx][ty + j]);
}

// ---------------- bf16 warp-MMA GEMM via ldmatrix (ALL GEMMs) ----------------
// D[m,n] = alpha * sum_k A[m,k]*B[n,k] (+ epilogue). Tile 128x128, K-slab 32,
// 8 warps (4m x 2n), warp 32x64. 3-stage cp.async pipeline, ONE sync per slab.
// EPI: 0 = alpha only
//      1 = +bias[m]
//      2 = +bias[n], split bf16 output: n<512 -> Cv, n>=512 -> C2v (fused QK)
//      3 = +bias[m] + resid[m,n] (fp32 out)
// OUTBF: 1 = bf16 packed output, 0 = fp32 output
#define LDPB 20
#define TILEB_BYTES (128 * LDPB * 4)
#define NSTAGE 3
#define MMB_SMEM (2 * NSTAGE * TILEB_BYTES)   // 61440

template<int EPI, int OUTBF>
__global__ __launch_bounds__(256, 2) void mmb_kernel(
    const __nv_bfloat16* __restrict__ A, const __nv_bfloat16* __restrict__ B,
    void* __restrict__ Cv, void* __restrict__ C2v,
    int Kd, int lda, int ldb, int ldc,
    size_t sA, size_t sB, size_t sC,
    float alpha, const float* __restrict__ bias,
    const float* __restrict__ resid, size_t sR)
{
    extern __shared__ uint32_t smu[];
    const uint32_t sbase = smem_u32(smu);

    const int t = threadIdx.x;
    const int lane = t & 31, wid = t >> 5;
    const int gid = lane >> 2, qid = lane & 3;
    const int wm = (wid & 3) * 32, wn = (wid >> 2) * 64;

    const int bz = blockIdx.z;
    const __nv_bfloat16* Ab = A + (size_t)bz * sA;
    const __nv_bfloat16* Bb = B + (size_t)bz * sB;
    const int m0 = blockIdx.y * 128;
    const int n0 = blockIdx.x * 128;

    const int lrow = t >> 2;
    const int lch  = t & 3;

    const int a_row  = wm + (lane & 15);
    const int a_uadd = (lane >> 4) << 2;            // u32 offset
    const int b_row  = wn + ((lane & 16) >> 1) + (lane & 7);
    const int b_uadd = (lane & 8) ? 4 : 0;

    float acc[2][8][4];
#pragma unroll
    for (int mi = 0; mi < 2; mi++)
#pragma unroll
        for (int ni = 0; ni < 8; ni++)
#pragma unroll
            for (int j = 0; j < 4; j++) acc[mi][ni][j] = 0.f;

    const int nslab = Kd >> 5;
    const uint32_t ld_off = (uint32_t)((lrow * LDPB + lch * 4) * 4);

    // prologue: issue slabs 0 and 1 (stages 0, 1)
#pragma unroll
    for (int s = 0; s < 2; s++) {
        const __nv_bfloat16* ga = Ab + (size_t)(m0 + lrow) * lda + (s << 5) + lch * 8;
        const __nv_bfloat16* gb = Bb + (size_t)(n0 + lrow) * ldb + (s << 5) + lch * 8;
        uint32_t da = sbase + (uint32_t)s * TILEB_BYTES + ld_off;
        uint32_t db = sbase + (uint32_t)(NSTAGE + s) * TILEB_BYTES + ld_off;
        cp_async16(da, ga);
        cp_async16(da + 64u * LDPB * 4u, ga + (size_t)64 * lda);
        cp_async16(db, gb);
        cp_async16(db + 64u * LDPB * 4u, gb + (size_t)64 * ldb);
        CP_COMMIT();
    }

    int stg = 0;          // stage of slab s
    int nstg = 2;         // stage for slab s+2
    for (int s = 0; s < nslab; s++) {
        CP_WAIT(1);          // slab s's group complete (only s+1 may remain)
        __syncthreads();     // all warps done computing slab s-1 -> stage nstg free

        if (s + 2 < nslab) {
            int k0 = (s + 2) << 5;
            const __nv_bfloat16* ga = Ab + (size_t)(m0 + lrow) * lda + k0 + lch * 8;
            const __nv_bfloat16* gb = Bb + (size_t)(n0 + lrow) * ldb + k0 + lch * 8;
            uint32_t da = sbase + (uint32_t)nstg * TILEB_BYTES + ld_off;
            uint32_t db = sbase + (uint32_t)(NSTAGE + nstg) * TILEB_BYTES + ld_off;
            cp_async16(da, ga);
            cp_async16(da + 64u * LDPB * 4u, ga + (size_t)64 * lda);
            cp_async16(db, gb);
            cp_async16(db + 64u * LDPB * 4u, gb + (size_t)64 * ldb);
        }
        CP_COMMIT();         // commit every iter (possibly empty) to keep group indices aligned

        const uint32_t abase = sbase + (uint32_t)stg * TILEB_BYTES;
        const uint32_t bbase = sbase + (uint32_t)(NSTAGE + stg) * TILEB_BYTES;
#pragma unroll
        for (int s2 = 0; s2 < 2; s2++) {
            const int kb = s2 * 8;
            uint32_t afr[2][4];
#pragma unroll
            for (int mi = 0; mi < 2; mi++)
                ldmx4(afr[mi], abase + (uint32_t)(((a_row + mi * 16) * LDPB + kb + a_uadd) * 4));
            uint32_t bfr[8][2];
#pragma unroll
            for (int nj = 0; nj < 4; nj++) {
                uint32_t r[4];
                ldmx4(r, bbase + (uint32_t)(((b_row + nj * 16) * LDPB + kb + b_uadd) * 4));
                bfr[2 * nj][0] = r[0]; bfr[2 * nj][1] = r[1];
                bfr[2 * nj + 1][0] = r[2]; bfr[2 * nj + 1][1] = r[3];
            }
#pragma unroll
            for (int mi = 0; mi < 2; mi++)
#pragma unroll
                for (int ni = 0; ni < 8; ni++)
                    mma_bf16(acc[mi][ni], afr[mi], bfr[ni]);
        }
        stg  = (stg  + 1 == NSTAGE) ? 0 : stg + 1;
        nstg = (nstg + 1 == NSTAGE) ? 0 : nstg + 1;
    }

    // epilogue
#pragma unroll
    for (int mi = 0; mi < 2; mi++) {
        const int r0 = m0 + wm + mi * 16 + gid;
        const int r1 = r0 + 8;
        float b0 = 0.f, b1 = 0.f;
        if (EPI == 1 || EPI == 3) { b0 = bias[r0]; b1 = bias[r1]; }
#pragma unroll
        for (int ni = 0; ni < 8; ni++) {
            const int col = n0 + wn + ni * 8 + 2 * qid;
            float o00 = acc[mi][ni][0] * alpha, o01 = acc[mi][ni][1] * alpha;
            float o10 = acc[mi][ni][2] * alpha, o11 = acc[mi][ni][3] * alpha;
            if (EPI == 1 || EPI == 3) { o00 += b0; o01 += b0; o10 += b1; o11 += b1; }
            if (EPI == 2) {
                float bn0 = bias[col], bn1 = bias[col + 1];
                o00 += bn0; o01 += bn1; o10 += bn0; o11 += bn1;
            }
            if (EPI == 2) {
                uint32_t* Cb;
                int cp;
                if (col < 512) { Cb = (uint32_t*)Cv  + (size_t)bz * (sC >> 1); cp = col >> 1; }
                else           { Cb = (uint32_t*)C2v + (size_t)bz * (sC >> 1); cp = (col - 512) >> 1; }
                Cb[(size_t)r0 * (ldc >> 1) + cp] = pack_bf2(o00, o01);
                Cb[(size_t)r1 * (ldc >> 1) + cp] = pack_bf2(o10, o11);
            } else if (OUTBF) {
                uint32_t* Cb = (uint32_t*)Cv + (size_t)bz * (sC >> 1);
                const int cp = col >> 1;
                Cb[(size_t)r0 * (ldc >> 1) + cp] = pack_bf2(o00, o01);
                Cb[(size_t)r1 * (ldc >> 1) + cp] = pack_bf2(o10, o11);
            } else {
                float* Cb = (float*)Cv + (size_t)bz * sC;
                if (EPI == 3) {
                    const float* rb = resid + (size_t)bz * sR;
                    float2 rv0 = *(const float2*)(rb + (size_t)r0 * ldc + col);
                    float2 rv1 = *(const float2*)(rb + (size_t)r1 * ldc + col);
                    o00 += rv0.x; o01 += rv0.y; o10 += rv1.x; o11 += rv1.y;
                }
                *(float2*)(Cb + (size_t)r0 * ldc + col) = make_float2(o00, o01);
                *(float2*)(Cb + (size_t)r1 * ldc + col) = make_float2(o10, o11);
            }
        }
    }
}

// ---------------- row softmax: bf16 g_p -> bf16 g_p (in place, fp32 math) ----------------
__global__ __launch_bounds__(256) void softmax_kernel() {
    uint4* row = (uint4*)(g_p + (size_t)blockIdx.x * HW);
    int t = threadIdx.x;
    uint4 u[2];
    float f[2][8];
    float mx = -1e30f;
#pragma unroll
    for (int i = 0; i < 2; i++) {
        u[i] = row[t + i * 256];
        float2 a0 = unpack_bf2(u[i].x), a1 = unpack_bf2(u[i].y);
        float2 a2 = unpack_bf2(u[i].z), a3 = unpack_bf2(u[i].w);
        f[i][0] = a0.x; f[i][1] = a0.y; f[i][2] = a1.x; f[i][3] = a1.y;
        f[i][4] = a2.x; f[i][5] = a2.y; f[i][6] = a3.x; f[i][7] = a3.y;
#pragma unroll
        for (int j = 0; j < 8; j++) mx = fmaxf(mx, f[i][j]);
    }
    __shared__ float sh[8];
#pragma unroll
    for (int o = 16; o; o >>= 1) mx = fmaxf(mx, __shfl_xor_sync(0xffffffffu, mx, o));
    if ((t & 31) == 0) sh[t >> 5] = mx;
    __syncthreads();
    mx = sh[0];
#pragma unroll
    for (int i = 1; i < 8; i++) mx = fmaxf(mx, sh[i]);

    float s = 0.f;
#pragma unroll
    for (int i = 0; i < 2; i++)
#pragma unroll
        for (int j = 0; j < 8; j++) {
            f[i][j] = __expf(f[i][j] - mx);
            s += f[i][j];
        }
#pragma unroll
    for (int o = 16; o; o >>= 1) s += __shfl_xor_sync(0xffffffffu, s, o);
    __syncthreads();
    if ((t & 31) == 0) sh[t >> 5] = s;
    __syncthreads();
    s = 0.f;
#pragma unroll
    for (int i = 0; i < 8; i++) s += sh[i];
    float inv = 1.f / s;
#pragma unroll
    for (int i = 0; i < 2; i++) {
        uint4 o;
        o.x = pack_bf2(f[i][0] * inv, f[i][1] * inv);
        o.y = pack_bf2(f[i][2] * inv, f[i][3] * inv);
        o.z = pack_bf2(f[i][4] * inv, f[i][5] * inv);
        o.w = pack_bf2(f[i][6] * inv, f[i][7] * inv);
        row[t + i * 256] = o;
    }
}

// ---------------- launch ----------------
extern "C" void kernel_launch(void* const* d_in, const int* in_sizes, int n_in,
                              void* d_out, int out_size) {
    const float* x     = (const float*)d_in[0];
    const float* gn_w  = (const float*)d_in[1];
    const float* gn_b  = (const float*)d_in[2];
    const float* qkv_w = (const float*)d_in[3];
    const float* qkv_b = (const float*)d_in[4];
    const float* out_w = (const float*)d_in[5];
    const float* out_b = (const float*)d_in[6];
    float* out = (float*)d_out;

    float *xn;
    __nv_bfloat16 *xnb, *q, *k, *v, *p, *ao, *wb, *wob;
    cudaGetSymbolAddress((void**)&xn,  g_xn);
    cudaGetSymbolAddress((void**)&xnb, g_xnb);
    cudaGetSymbolAddress((void**)&q,   g_q);
    cudaGetSymbolAddress((void**)&k,   g_k);
    cudaGetSymbolAddress((void**)&v,   g_v);
    cudaGetSymbolAddress((void**)&p,   g_p);
    cudaGetSymbolAddress((void**)&ao,  g_ao);
    cudaGetSymbolAddress((void**)&wb,  g_wb);
    cudaGetSymbolAddress((void**)&wob, g_wob);

    cudaFuncSetAttribute(mmb_kernel<2,1>, cudaFuncAttributeMaxDynamicSharedMemorySize, MMB_SMEM);
    cudaFuncSetAttribute(mmb_kernel<1,1>, cudaFuncAttributeMaxDynamicSharedMemorySize, MMB_SMEM);
    cudaFuncSetAttribute(mmb_kernel<0,1>, cudaFuncAttributeMaxDynamicSharedMemorySize, MMB_SMEM);
    cudaFuncSetAttribute(mmb_kernel<3,0>, cudaFuncAttributeMaxDynamicSharedMemorySize, MMB_SMEM);

    const size_t sXN = (size_t)CCH * HW;
    const size_t sSC = (size_t)HW * HW;

    // 0) weight prep (all bf16)
    prep_wb_kernel<<<(3 * CCH * CCH + 255) / 256, 256>>>(qkv_w, wb, 3 * CCH * CCH);
    prep_wb_kernel<<<(CCH * CCH + 255) / 256, 256>>>(out_w, wob, CCH * CCH);

    // 1) GroupNorm
    gn_kernel<<<BATCH * NGRP, 256>>>(x, gn_w, gn_b);
    // 2) transpose -> xnb (bf16)
    tr_kernel<<<dim3(HW / 32, CCH / 32, BATCH), 256>>>();

    // 3) fused Q,K projection: N=1024 over [Wq;Wk], bias[n], split bf16 out
    mmb_kernel<2,1><<<dim3(1024 / 128, HW / 128, BATCH), 256, MMB_SMEM>>>(
        xnb, wb, q, k, CCH, CCH, CCH, CCH, sXN, 0, sXN, 1.f, qkv_b, nullptr, 0);

    // 4) V[c,j] = Wv[c,:] . xn[:,j] + bv
    mmb_kernel<1,1><<<dim3(HW / 128, CCH / 128, BATCH), 256, MMB_SMEM>>>(
        wb + (size_t)2 * CCH * CCH, xnb, v, nullptr, CCH, CCH, CCH, HW, 0, sXN, sXN,
        1.f, qkv_b + 2 * CCH, nullptr, 0);

    // 5) scores[i,j] = scale * Q[i,:].K[j,:]  (bf16 MMA, bf16 out directly to g_p)
    mmb_kernel<0,1><<<dim3(HW / 128, HW / 128, BATCH), 256, MMB_SMEM>>>(
        q, k, p, nullptr, CCH, CCH, CCH, HW, sXN, sXN, sSC,
        0.044194173824159216f, nullptr, nullptr, 0);

    // 6) softmax in-place on bf16 g_p
    softmax_kernel<<<BATCH * HW, 256>>>();

    // 7) ao[i,c] = P[i,:] . V[c,:]
    mmb_kernel<0,1><<<dim3(CCH / 128, HW / 128, BATCH), 256, MMB_SMEM>>>(
        p, v, ao, nullptr, HW, HW, HW, CCH, sSC, sXN, sXN, 1.f, nullptr, nullptr, 0);

    // 8) out[o,i] = Wo[o,:] . ao[i,:] + bo + xn[o,i]
    mmb_kernel<3,0><<<dim3(HW / 128, CCH / 128, BATCH), 256, MMB_SMEM>>>(
        wob, ao, out, nullptr, CCH, CCH, CCH, HW, 0, sXN, sXN, 1.f, out_b, xn, sXN);
}